// round 1
// baseline (speedup 1.0000x reference)
#include <cuda_runtime.h>
#include <math.h>

// ---------------- problem constants ----------------
#define LSEQ 2048
#define BB   8
#define DD   1024
#define ZZ   128
#define HH   2048
#define NN   16
#define MROWS (LSEQ*BB)           // 16384
#define NBASE (ZZ+HH+2*DD)        // 4224

// ---------------- scratch (static device globals; no runtime alloc) ----------------
__device__ float g_xn  [(size_t)MROWS*DD];        // 64 MB
__device__ float g_mx  [(size_t)MROWS*DD];        // 64 MB
__device__ float g_v   [(size_t)MROWS*HH];        // 128 MB  (L,B,H)
__device__ float g_u   [(size_t)MROWS*DD];        // 64 MB
__device__ float g_r   [(size_t)MROWS*HH];        // 128 MB
__device__ float g_hx  [(size_t)MROWS*DD];        // 64 MB
__device__ float g_q   [(size_t)BB*LSEQ*ZZ];      // 8 MB   (B,L,Z)
__device__ float g_k   [(size_t)BB*LSEQ*ZZ];      // 8 MB
__device__ float g_attn[(size_t)BB*LSEQ*LSEQ];    // 134 MB (B,L,L)
__device__ float g_h   [(size_t)BB*LSEQ*HH];      // 134 MB (B,L,H)

// ---------------- math helpers ----------------
__device__ __forceinline__ float sigm_(float x){ return 1.f/(1.f+expf(-x)); }
__device__ __forceinline__ float silu_(float x){ return x/(1.f+expf(-x)); }
__device__ __forceinline__ float laplace_(float x){
    const float inv = (float)(1.0/(0.282095*1.4142135623730951));
    return 0.5f*(1.f + erff((x - 0.707107f) * inv));
}

// ---------------- LayerNorm: one block per (l,b) row ----------------
__global__ __launch_bounds__(256) void ln_kernel(
    const float* __restrict__ x, const float* __restrict__ w,
    const float* __restrict__ b, float* __restrict__ out)
{
    long row = blockIdx.x;
    int tid = threadIdx.x;
    const float4* xr = (const float4*)(x + row*DD);
    float4 v = xr[tid];
    float s  = v.x+v.y+v.z+v.w;
    float ss = fmaf(v.x,v.x, fmaf(v.y,v.y, fmaf(v.z,v.z, v.w*v.w)));
    #pragma unroll
    for (int o=16;o>0;o>>=1){
        s  += __shfl_xor_sync(0xffffffffu, s, o);
        ss += __shfl_xor_sync(0xffffffffu, ss, o);
    }
    __shared__ float sh0[8], sh1[8];
    int wid = tid>>5, lane = tid&31;
    if (lane==0){ sh0[wid]=s; sh1[wid]=ss; }
    __syncthreads();
    float S=0.f, SS=0.f;
    #pragma unroll
    for (int i=0;i<8;i++){ S += sh0[i]; SS += sh1[i]; }
    float mu  = S*(1.f/DD);
    float var = SS*(1.f/DD) - mu*mu;
    float inv = rsqrtf(var + 1e-5f);
    float4 wv = ((const float4*)w)[tid];
    float4 bv = ((const float4*)b)[tid];
    float4 o;
    o.x = (v.x-mu)*inv*wv.x + bv.x;
    o.y = (v.y-mu)*inv*wv.y + bv.y;
    o.z = (v.z-mu)*inv*wv.z + bv.z;
    o.w = (v.w-mu)*inv*wv.w + bv.w;
    ((float4*)(out + row*DD))[tid] = o;
}

// ---------------- EMA: 16-state recurrence, one thread per (b,d) ----------------
__global__ __launch_bounds__(256) void ema_kernel(
    const float* __restrict__ xn,
    const float* __restrict__ delta, const float* __restrict__ alpha,
    const float* __restrict__ beta_e, const float* __restrict__ gamma_e,
    const float* __restrict__ omega, float* __restrict__ mx)
{
    int gid = blockIdx.x*blockDim.x + threadIdx.x;   // 0..8191 = b*1024+d
    int d = gid & (DD-1);
    float q[NN], pb[NN], g[NN], s[NN];
    #pragma unroll
    for (int n=0;n<NN;n++){
        float de = delta[d*NN+n];
        float p  = sigm_(de);
        q[n]  = 1.f - p*sigm_(alpha[d*NN+n]);
        pb[n] = p*beta_e[d*NN+n];
        g[n]  = gamma_e[d*NN+n]*0.25f;   // 1/sqrt(16)
        s[n]  = 0.f;
    }
    float om = omega[d];
    const float* xp = xn + gid;
    float* op = mx + gid;
    for (int l0=0; l0<LSEQ; l0+=8){
        float xv[8];
        #pragma unroll
        for (int i=0;i<8;i++) xv[i] = xp[(size_t)(l0+i)*(BB*DD)];
        #pragma unroll
        for (int i=0;i<8;i++){
            float xc = xv[i];
            float a0=0.f,a1=0.f,a2=0.f,a3=0.f;
            #pragma unroll
            for (int n=0;n<NN;n+=4){
                s[n]   = fmaf(q[n],   s[n],   pb[n]*xc);
                s[n+1] = fmaf(q[n+1], s[n+1], pb[n+1]*xc);
                s[n+2] = fmaf(q[n+2], s[n+2], pb[n+2]*xc);
                s[n+3] = fmaf(q[n+3], s[n+3], pb[n+3]*xc);
                a0 = fmaf(g[n],   s[n],   a0);
                a1 = fmaf(g[n+1], s[n+1], a1);
                a2 = fmaf(g[n+2], s[n+2], a2);
                a3 = fmaf(g[n+3], s[n+3], a3);
            }
            float y = (a0+a1)+(a2+a3) + om*xc;
            op[(size_t)(l0+i)*(BB*DD)] = silu_(y);
        }
    }
}

// ---------------- generic fp32 GEMM, 128x128x16, 8x8/thread ----------------
struct EpiP {
    float* c0; float* c1; float* c2; float* c3; float* c4;
    const float* bias; const float* aux0; const float* aux1; const float* aux2;
    const float* rbuf;
    long strideC; int ldc;
};

// EPI: 0 = silu(acc+bias) -> c0          (v GEMM)
//      1 = base split: u / q,k / r / hx  (base GEMM)
//      2 = laplace(acc/L + rel_pos)      (qk GEMM, batched)
//      3 = plain store (batched)         (attn @ v)
//      4 = out = x + u*(silu(hx+acc+h_b) - x)   (final GEMM, ASRC=1: A = h*r)
template<int TRANSB, int ASRC, int EPI>
__global__ __launch_bounds__(256) void gemm_k(
    const float* __restrict__ A, const float* __restrict__ B,
    int lda, int ldb, int K, long sA, long sB, EpiP P)
{
    constexpr int BM=128, BN=128, BK=16, PAD=4;
    __shared__ float As[2][BK][BM+PAD];
    __shared__ float Bs[2][BK][BN+PAD];
    const int tid = threadIdx.x;
    const int tx = tid & 15, ty = tid >> 4;
    const int m0 = blockIdx.y * BM, n0 = blockIdx.x * BN;
    const int bz = blockIdx.z;
    A += (long)bz * sA;
    B += (long)bz * sB;

    float acc[8][8];
    #pragma unroll
    for (int i=0;i<8;i++)
        #pragma unroll
        for (int j=0;j<8;j++) acc[i][j]=0.f;

    const int am = tid >> 4;      // A: row-within-tile base (0..15)
    const int ak = tid & 15;      // A: k-within-tile
    const int bk0 = tid >> 7;     // B (no trans): k base (0..1)
    const int bn  = tid & 127;    // B (no trans): col

    float ra[8], rb[8];

    auto fetchA = [&](int k0){
        #pragma unroll
        for (int i=0;i<8;i++){
            int gm = m0 + am + i*16;
            float v = A[(long)gm*lda + k0 + ak];
            if (ASRC==1){
                int b = gm >> 11, l = gm & (LSEQ-1);
                v *= P.rbuf[(long)((l<<3)+b)*lda + k0 + ak];
            }
            ra[i] = v;
        }
    };
    auto fetchB = [&](int k0){
        #pragma unroll
        for (int i=0;i<8;i++){
            if (TRANSB==0)
                rb[i] = B[(long)(k0 + bk0 + i*2)*ldb + n0 + bn];
            else
                rb[i] = B[(long)(n0 + am + i*16)*ldb + k0 + ak];
        }
    };
    auto storeA = [&](int st){
        #pragma unroll
        for (int i=0;i<8;i++) As[st][ak][am + i*16] = ra[i];
    };
    auto storeB = [&](int st){
        #pragma unroll
        for (int i=0;i<8;i++){
            if (TRANSB==0) Bs[st][bk0 + i*2][bn] = rb[i];
            else           Bs[st][ak][am + i*16] = rb[i];
        }
    };

    fetchA(0); fetchB(0);
    storeA(0); storeB(0);
    __syncthreads();

    const int nk = K / BK;
    for (int kt=0; kt<nk; kt++){
        const int cur = kt & 1;
        if (kt+1 < nk){ fetchA((kt+1)*BK); fetchB((kt+1)*BK); }
        #pragma unroll
        for (int kk=0;kk<BK;kk++){
            float4 a0 = *(const float4*)&As[cur][kk][ty*8];
            float4 a1 = *(const float4*)&As[cur][kk][ty*8+4];
            float4 b0 = *(const float4*)&Bs[cur][kk][tx*8];
            float4 b1 = *(const float4*)&Bs[cur][kk][tx*8+4];
            float av[8] = {a0.x,a0.y,a0.z,a0.w,a1.x,a1.y,a1.z,a1.w};
            float bv[8] = {b0.x,b0.y,b0.z,b0.w,b1.x,b1.y,b1.z,b1.w};
            #pragma unroll
            for (int i=0;i<8;i++)
                #pragma unroll
                for (int j=0;j<8;j++)
                    acc[i][j] = fmaf(av[i], bv[j], acc[i][j]);
        }
        if (kt+1 < nk){ storeA((kt+1)&1); storeB((kt+1)&1); }
        __syncthreads();
    }

    // ---------------- epilogue ----------------
    #pragma unroll
    for (int ii=0;ii<8;ii++){
        int gi = m0 + ty*8 + ii;
        #pragma unroll
        for (int jj=0;jj<8;jj++){
            int gj = n0 + tx*8 + jj;
            float val = acc[ii][jj];
            if (EPI==0){
                P.c0[(long)gi*P.ldc + gj] = silu_(val + P.bias[gj]);
            } else if (EPI==1){
                int l = gi>>3, b = gi&7;
                float vb = val + P.bias[gj];
                if (gj < DD){
                    P.c0[(long)gi*DD + gj] = sigm_(vb);
                } else if (gj < DD+ZZ){
                    int zi = gj - DD;
                    float zv = silu_(vb);
                    long qi = ((long)b*LSEQ + l)*ZZ + zi;
                    P.c1[qi] = zv*P.aux0[zi]     + P.aux1[zi];
                    P.c2[qi] = zv*P.aux0[ZZ+zi]  + P.aux1[ZZ+zi];
                } else if (gj < DD+ZZ+HH){
                    P.c3[(long)gi*HH + (gj - (DD+ZZ))] = silu_(vb);
                } else {
                    P.c4[(long)gi*DD + (gj - (DD+ZZ+HH))] = vb;
                }
            } else if (EPI==2){
                float s = val*(1.0f/LSEQ) + P.aux0[(LSEQ-1) + gj - gi];
                P.c0[(long)bz*P.strideC + (long)gi*P.ldc + gj] = laplace_(s);
            } else if (EPI==3){
                P.c0[(long)bz*P.strideC + (long)gi*P.ldc + gj] = val;
            } else {
                int b = gi>>11, l = gi & (LSEQ-1);
                long rlb = (long)((l<<3)+b);
                float t  = P.aux0[rlb*DD + gj] + val + P.bias[gj];
                float h2 = silu_(t);
                float xv = P.aux2[rlb*DD + gj];
                P.c0[rlb*DD + gj] = xv + P.aux1[rlb*DD + gj]*(h2 - xv);
            }
        }
    }
}

// ---------------- host launcher ----------------
extern "C" void kernel_launch(void* const* d_in, const int* in_sizes, int n_in,
                              void* d_out, int out_size)
{
    const float* x      = (const float*)d_in[0];
    const float* delta  = (const float*)d_in[1];
    const float* alpha  = (const float*)d_in[2];
    const float* beta_e = (const float*)d_in[3];
    const float* gamma_e= (const float*)d_in[4];
    const float* omega  = (const float*)d_in[5];
    const float* v_w    = (const float*)d_in[6];
    const float* v_b    = (const float*)d_in[7];
    const float* mx_w   = (const float*)d_in[8];
    const float* mx_b   = (const float*)d_in[9];
    const float* h_w    = (const float*)d_in[10];
    const float* h_b    = (const float*)d_in[11];
    const float* qk_g   = (const float*)d_in[12];
    const float* qk_b   = (const float*)d_in[13];
    const float* rel    = (const float*)d_in[14];
    const float* ln_w   = (const float*)d_in[15];
    const float* ln_b   = (const float*)d_in[16];
    float* out = (float*)d_out;

    float *xn,*mx,*v,*u,*r,*hx,*qb,*kb,*attn,*hbuf;
    cudaGetSymbolAddress((void**)&xn,   g_xn);
    cudaGetSymbolAddress((void**)&mx,   g_mx);
    cudaGetSymbolAddress((void**)&v,    g_v);
    cudaGetSymbolAddress((void**)&u,    g_u);
    cudaGetSymbolAddress((void**)&r,    g_r);
    cudaGetSymbolAddress((void**)&hx,   g_hx);
    cudaGetSymbolAddress((void**)&qb,   g_q);
    cudaGetSymbolAddress((void**)&kb,   g_k);
    cudaGetSymbolAddress((void**)&attn, g_attn);
    cudaGetSymbolAddress((void**)&hbuf, g_h);

    // 1) layernorm
    ln_kernel<<<MROWS, 256>>>(x, ln_w, ln_b, xn);

    // 2) EMA recurrence + silu
    ema_kernel<<<(BB*DD)/256, 256>>>(xn, delta, alpha, beta_e, gamma_e, omega, mx);

    // 3) v = silu(xn @ v_w + v_b)   [M=16384, N=2048, K=1024]
    {
        EpiP P = {}; P.c0 = v; P.bias = v_b; P.ldc = HH;
        gemm_k<0,0,0><<<dim3(HH/128, MROWS/128, 1), 256>>>(xn, v_w, DD, HH, DD, 0, 0, P);
    }
    // 4) base = mx @ mx_w + mx_b, split epilogue  [M=16384, N=4224, K=1024]
    {
        EpiP P = {}; P.c0=u; P.c1=qb; P.c2=kb; P.c3=r; P.c4=hx;
        P.bias=mx_b; P.aux0=qk_g; P.aux1=qk_b;
        gemm_k<0,0,1><<<dim3(NBASE/128, MROWS/128, 1), 256>>>(mx, mx_w, DD, NBASE, DD, 0, 0, P);
    }
    // 5) attn = laplace(q @ k^T / L + bias)  [batched B=8, M=N=2048, K=128]
    {
        EpiP P = {}; P.c0 = attn; P.aux0 = rel; P.ldc = LSEQ;
        P.strideC = (long)LSEQ*LSEQ;
        gemm_k<1,0,2><<<dim3(LSEQ/128, LSEQ/128, BB), 256>>>(
            qb, kb, ZZ, ZZ, ZZ, (long)LSEQ*ZZ, (long)LSEQ*ZZ, P);
    }
    // 6) h = attn @ vb  [batched B=8, M=2048, N=2048, K=2048]; vb[b][m][h] = v[(m*8+b)*H + h]
    {
        EpiP P = {}; P.c0 = hbuf; P.ldc = HH;
        P.strideC = (long)LSEQ*HH;
        gemm_k<0,0,3><<<dim3(HH/128, LSEQ/128, BB), 256>>>(
            attn, v, LSEQ, BB*HH, LSEQ, (long)LSEQ*LSEQ, (long)HH, P);
    }
    // 7) out = x + u*(silu(hx + (h*r)@h_w + h_b) - x)  [M=16384, N=1024, K=2048]
    {
        EpiP P = {}; P.c0 = out; P.bias = h_b; P.aux0 = hx; P.aux1 = u; P.aux2 = x;
        P.rbuf = r;
        gemm_k<0,1,4><<<dim3(DD/128, MROWS/128, 1), 256>>>(hbuf, h_w, HH, DD, HH, 0, 0, P);
    }
}

// round 3
// speedup vs baseline: 1.9890x; 1.9890x over previous
#include <cuda_runtime.h>
#include <cuda_bf16.h>
#include <math.h>
#include <stdint.h>

// ---------------- problem constants ----------------
#define LSEQ 2048
#define BB   8
#define DD   1024
#define ZZ   128
#define HH   2048
#define NN   16
#define MROWS (LSEQ*BB)           // 16384
#define NBASE (ZZ+HH+2*DD)        // 4224

// ---------------- scratch ----------------
__device__ float g_xn  [(size_t)MROWS*DD];
__device__ float g_mx  [(size_t)MROWS*DD];
__device__ float g_v   [(size_t)MROWS*HH];        // (L,B,H)
__device__ float g_vT  [(size_t)BB*HH*LSEQ];      // (B,H,L)
__device__ float g_u   [(size_t)MROWS*DD];
__device__ float g_r   [(size_t)MROWS*HH];
__device__ float g_hx  [(size_t)MROWS*DD];
__device__ float g_q   [(size_t)BB*LSEQ*ZZ];
__device__ float g_k   [(size_t)BB*LSEQ*ZZ];
__device__ float g_attn[(size_t)BB*LSEQ*LSEQ];
__device__ float g_hr  [(size_t)MROWS*HH];        // (L,B,H) h*r
__device__ float g_vwT [(size_t)HH*DD];
__device__ float g_mxwT[(size_t)NBASE*DD];
__device__ float g_hwT [(size_t)DD*HH];

// ---------------- math helpers ----------------
__device__ __forceinline__ float sigm_(float x){ return 1.f/(1.f+expf(-x)); }
__device__ __forceinline__ float silu_(float x){ return x/(1.f+expf(-x)); }
__device__ __forceinline__ float laplace_(float x){
    const float inv = (float)(1.0/(0.282095*1.4142135623730951));
    return 0.5f*(1.f + erff((x - 0.707107f) * inv));
}

__device__ __forceinline__ uint32_t sm_u32(const void* p){
    uint32_t a;
    asm("{ .reg .u64 t; cvta.to.shared.u64 t, %1; cvt.u32.u64 %0, t; }" : "=r"(a) : "l"(p));
    return a;
}

__device__ __forceinline__ void ldm4(uint32_t* r, uint32_t addr){
    asm volatile("ldmatrix.sync.aligned.m8n8.x4.shared.b16 {%0,%1,%2,%3}, [%4];"
        : "=r"(r[0]),"=r"(r[1]),"=r"(r[2]),"=r"(r[3]) : "r"(addr));
}

__device__ __forceinline__ void mma16816(float* c, const uint32_t* a, uint32_t b0, uint32_t b1){
    asm volatile("mma.sync.aligned.m16n8k16.row.col.f32.bf16.bf16.f32 "
        "{%0,%1,%2,%3}, {%4,%5,%6,%7}, {%8,%9}, {%0,%1,%2,%3};"
        : "+f"(c[0]),"+f"(c[1]),"+f"(c[2]),"+f"(c[3])
        : "r"(a[0]),"r"(a[1]),"r"(a[2]),"r"(a[3]),"r"(b0),"r"(b1));
}

__device__ __forceinline__ void split4(float4 v, uint2& h, uint2& l){
    __nv_bfloat16 h0=__float2bfloat16(v.x), h1=__float2bfloat16(v.y),
                  h2=__float2bfloat16(v.z), h3=__float2bfloat16(v.w);
    float l0=v.x-__bfloat162float(h0), l1=v.y-__bfloat162float(h1),
          l2=v.z-__bfloat162float(h2), l3=v.w-__bfloat162float(h3);
    __nv_bfloat16 g0=__float2bfloat16(l0), g1=__float2bfloat16(l1),
                  g2=__float2bfloat16(l2), g3=__float2bfloat16(l3);
    h.x = (uint32_t)__bfloat16_as_ushort(h0) | ((uint32_t)__bfloat16_as_ushort(h1)<<16);
    h.y = (uint32_t)__bfloat16_as_ushort(h2) | ((uint32_t)__bfloat16_as_ushort(h3)<<16);
    l.x = (uint32_t)__bfloat16_as_ushort(g0) | ((uint32_t)__bfloat16_as_ushort(g1)<<16);
    l.y = (uint32_t)__bfloat16_as_ushort(g2) | ((uint32_t)__bfloat16_as_ushort(g3)<<16);
}

// ---------------- LayerNorm ----------------
__global__ __launch_bounds__(256) void ln_kernel(
    const float* __restrict__ x, const float* __restrict__ w,
    const float* __restrict__ b, float* __restrict__ out)
{
    long row = blockIdx.x;
    int tid = threadIdx.x;
    const float4* xr = (const float4*)(x + row*DD);
    float4 v = xr[tid];
    float s  = v.x+v.y+v.z+v.w;
    float ss = fmaf(v.x,v.x, fmaf(v.y,v.y, fmaf(v.z,v.z, v.w*v.w)));
    #pragma unroll
    for (int o=16;o>0;o>>=1){
        s  += __shfl_xor_sync(0xffffffffu, s, o);
        ss += __shfl_xor_sync(0xffffffffu, ss, o);
    }
    __shared__ float sh0[8], sh1[8];
    int wid = tid>>5, lane = tid&31;
    if (lane==0){ sh0[wid]=s; sh1[wid]=ss; }
    __syncthreads();
    float S=0.f, SS=0.f;
    #pragma unroll
    for (int i=0;i<8;i++){ S += sh0[i]; SS += sh1[i]; }
    float mu  = S*(1.f/DD);
    float var = SS*(1.f/DD) - mu*mu;
    float inv = rsqrtf(var + 1e-5f);
    float4 wv = ((const float4*)w)[tid];
    float4 bv = ((const float4*)b)[tid];
    float4 o;
    o.x = (v.x-mu)*inv*wv.x + bv.x;
    o.y = (v.y-mu)*inv*wv.y + bv.y;
    o.z = (v.z-mu)*inv*wv.z + bv.z;
    o.w = (v.w-mu)*inv*wv.w + bv.w;
    ((float4*)(out + row*DD))[tid] = o;
}

// ---------------- EMA ----------------
__global__ __launch_bounds__(256) void ema_kernel(
    const float* __restrict__ xn,
    const float* __restrict__ delta, const float* __restrict__ alpha,
    const float* __restrict__ beta_e, const float* __restrict__ gamma_e,
    const float* __restrict__ omega, float* __restrict__ mx)
{
    int gid = blockIdx.x*blockDim.x + threadIdx.x;   // b*1024+d
    int d = gid & (DD-1);
    float q[NN], pb[NN], g[NN], s[NN];
    #pragma unroll
    for (int n=0;n<NN;n++){
        float de = delta[d*NN+n];
        float p  = sigm_(de);
        q[n]  = 1.f - p*sigm_(alpha[d*NN+n]);
        pb[n] = p*beta_e[d*NN+n];
        g[n]  = gamma_e[d*NN+n]*0.25f;
        s[n]  = 0.f;
    }
    float om = omega[d];
    const float* xp = xn + gid;
    float* op = mx + gid;
    for (int l0=0; l0<LSEQ; l0+=8){
        float xv[8];
        #pragma unroll
        for (int i=0;i<8;i++) xv[i] = xp[(size_t)(l0+i)*(BB*DD)];
        #pragma unroll
        for (int i=0;i<8;i++){
            float xc = xv[i];
            float a0=0.f,a1=0.f,a2=0.f,a3=0.f;
            #pragma unroll
            for (int n=0;n<NN;n+=4){
                s[n]   = fmaf(q[n],   s[n],   pb[n]*xc);
                s[n+1] = fmaf(q[n+1], s[n+1], pb[n+1]*xc);
                s[n+2] = fmaf(q[n+2], s[n+2], pb[n+2]*xc);
                s[n+3] = fmaf(q[n+3], s[n+3], pb[n+3]*xc);
                a0 = fmaf(g[n],   s[n],   a0);
                a1 = fmaf(g[n+1], s[n+1], a1);
                a2 = fmaf(g[n+2], s[n+2], a2);
                a3 = fmaf(g[n+3], s[n+3], a3);
            }
            float y = (a0+a1)+(a2+a3) + om*xc;
            op[(size_t)(l0+i)*(BB*DD)] = silu_(y);
        }
    }
}

// ---------------- transposes ----------------
__global__ __launch_bounds__(256) void tr_w(const float* __restrict__ in, float* __restrict__ out,
                                            int R, int C)
{
    __shared__ float t[32][33];
    int c0 = blockIdx.x*32, r0 = blockIdx.y*32;
    int tx = threadIdx.x, ty = threadIdx.y;
    #pragma unroll
    for (int k=0;k<4;k++)
        t[ty+8*k][tx] = in[(size_t)(r0+ty+8*k)*C + c0+tx];
    __syncthreads();
    #pragma unroll
    for (int k=0;k<4;k++)
        out[(size_t)(c0+ty+8*k)*R + r0+tx] = t[tx][ty+8*k];
}

__global__ __launch_bounds__(256) void tr_v(const float* __restrict__ v, float* __restrict__ vT)
{
    __shared__ float t[32][33];
    int h0 = blockIdx.x*32, l0 = blockIdx.y*32, b = blockIdx.z;
    int tx = threadIdx.x, ty = threadIdx.y;
    #pragma unroll
    for (int k=0;k<4;k++)
        t[ty+8*k][tx] = v[((size_t)(l0+ty+8*k)*8 + b)*HH + h0+tx];
    __syncthreads();
    #pragma unroll
    for (int k=0;k<4;k++)
        vT[(size_t)b*HH*LSEQ + (size_t)(h0+ty+8*k)*LSEQ + l0+tx] = t[tx][ty+8*k];
}

// ---------------- mma.sync GEMM, 128x128x32, bf16 hi/lo 3-term split ----------------
// smem: per stage 40960 B: AH(10240) AL(10240) BH(10240) BL(10240); rows padded to 80 B.
struct EpiP {
    float* c0; float* c1; float* c2; float* c3; float* c4;
    const float* bias; const float* aux0; const float* aux1; const float* aux2;
    long strideC; int ldc;
};

#define ROWB 80
#define TILEB 10240
#define STAGEB 40960

template<int EPI>
__global__ __launch_bounds__(256) void gemm_mma(
    const float* __restrict__ A, const float* __restrict__ B,
    int lda, int ldb, int K, long sA, long sB, EpiP P)
{
    extern __shared__ char sm[];
    const uint32_t smb = sm_u32(sm);
    const int tid = threadIdx.x;
    const int w = tid>>5, lane = tid&31;
    const int m0 = blockIdx.y*128, n0 = blockIdx.x*128, bz = blockIdx.z;
    A += (size_t)bz * sA;
    B += (size_t)bz * sB;
    const int mw = (w&1)*64, nw = (w>>1)*32;

    // global staging: thread loads 16 floats from A row (tid>>1), 16 from B row (tid>>1)
    const int lrow = tid>>1, lcol = (tid&1)*16;
    const float* Ap = A + (size_t)(m0+lrow)*lda + lcol;
    const float* Bp = B + (size_t)(n0+lrow)*ldb + lcol;
    const uint32_t stoff = lrow*ROWB + (tid&1)*32;

    // ldmatrix per-lane base offsets (bytes within a tile buffer)
    const uint32_t aoff = (uint32_t)((mw + (lane&7) + ((lane>>3)&1)*8)*ROWB + ((lane>>4)&1)*16);
    const uint32_t boff = (uint32_t)((nw + (lane&7) + ((lane>>4)&1)*8)*ROWB + ((lane>>3)&1)*16);

    float acc[4][4][4];
    #pragma unroll
    for (int a=0;a<4;a++)
        #pragma unroll
        for (int n=0;n<4;n++)
            #pragma unroll
            for (int i=0;i<4;i++) acc[a][n][i]=0.f;

    float4 av[4], bv[4];
    #pragma unroll
    for (int g=0;g<4;g++){ av[g] = *(const float4*)(Ap + g*4); bv[g] = *(const float4*)(Bp + g*4); }
    {
        char* base = sm;
        #pragma unroll
        for (int g=0;g<4;g++){
            uint2 h,l;
            split4(av[g], h, l);
            *(uint2*)(base + stoff + g*8) = h;
            *(uint2*)(base + TILEB + stoff + g*8) = l;
            split4(bv[g], h, l);
            *(uint2*)(base + 2*TILEB + stoff + g*8) = h;
            *(uint2*)(base + 3*TILEB + stoff + g*8) = l;
        }
    }
    __syncthreads();

    const int nk = K/32;
    for (int kt=0; kt<nk; kt++){
        if (kt+1 < nk){
            const float* An = Ap + (size_t)(kt+1)*32;
            const float* Bn = Bp + (size_t)(kt+1)*32;
            #pragma unroll
            for (int g=0;g<4;g++){ av[g] = *(const float4*)(An + g*4); bv[g] = *(const float4*)(Bn + g*4); }
        }
        const uint32_t stb = smb + (kt&1)*STAGEB;
        const uint32_t Ah = stb + aoff, Al = Ah + TILEB;
        const uint32_t Bh = stb + 2*TILEB + boff, Bl = Bh + TILEB;
        #pragma unroll
        for (int ks=0; ks<2; ks++){
            uint32_t ah[4][4], al[4][4], bh[2][4], bl[2][4];
            #pragma unroll
            for (int a=0;a<4;a++){
                ldm4(ah[a], Ah + a*(16*ROWB) + ks*32);
                ldm4(al[a], Al + a*(16*ROWB) + ks*32);
            }
            #pragma unroll
            for (int p=0;p<2;p++){
                ldm4(bh[p], Bh + p*(16*ROWB) + ks*32);
                ldm4(bl[p], Bl + p*(16*ROWB) + ks*32);
            }
            #pragma unroll
            for (int a=0;a<4;a++){
                #pragma unroll
                for (int n=0;n<4;n++){
                    const int p=n>>1, q=(n&1)*2;
                    mma16816(acc[a][n], ah[a], bh[p][q], bh[p][q+1]);
                    mma16816(acc[a][n], al[a], bh[p][q], bh[p][q+1]);
                    mma16816(acc[a][n], ah[a], bl[p][q], bl[p][q+1]);
                }
            }
        }
        if (kt+1 < nk){
            char* base = sm + ((kt+1)&1)*STAGEB;
            #pragma unroll
            for (int g=0;g<4;g++){
                uint2 h,l;
                split4(av[g], h, l);
                *(uint2*)(base + stoff + g*8) = h;
                *(uint2*)(base + TILEB + stoff + g*8) = l;
                split4(bv[g], h, l);
                *(uint2*)(base + 2*TILEB + stoff + g*8) = h;
                *(uint2*)(base + 3*TILEB + stoff + g*8) = l;
            }
        }
        __syncthreads();
    }

    // ---------------- epilogue ----------------
    #pragma unroll
    for (int a=0;a<4;a++){
        #pragma unroll
        for (int n=0;n<4;n++){
            const int gj = n0 + nw + n*8 + (lane&3)*2;
            #pragma unroll
            for (int half=0; half<2; half++){
                const int gi = m0 + mw + a*16 + (lane>>2) + half*8;
                float v0 = acc[a][n][half*2+0];
                float v1 = acc[a][n][half*2+1];
                if (EPI==0){
                    float2 o = { silu_(v0 + P.bias[gj]), silu_(v1 + P.bias[gj+1]) };
                    *(float2*)&P.c0[(size_t)gi*P.ldc + gj] = o;
                } else if (EPI==1){
                    v0 += P.bias[gj]; v1 += P.bias[gj+1];
                    if (n0 < DD){
                        float2 o = { sigm_(v0), sigm_(v1) };
                        *(float2*)&P.c0[(size_t)gi*DD + gj] = o;
                    } else if (n0 < DD+ZZ){
                        int zi = gj - DD;
                        int l = gi>>3, b = gi&7;
                        size_t qi = ((size_t)b*LSEQ + l)*ZZ + zi;
                        float z0 = silu_(v0), z1 = silu_(v1);
                        float2 qv = { z0*P.aux0[zi]   + P.aux1[zi],
                                      z1*P.aux0[zi+1] + P.aux1[zi+1] };
                        float2 kv = { z0*P.aux0[ZZ+zi]   + P.aux1[ZZ+zi],
                                      z1*P.aux0[ZZ+zi+1] + P.aux1[ZZ+zi+1] };
                        *(float2*)&P.c1[qi] = qv;
                        *(float2*)&P.c2[qi] = kv;
                    } else if (n0 < DD+ZZ+HH){
                        float2 o = { silu_(v0), silu_(v1) };
                        *(float2*)&P.c3[(size_t)gi*HH + (gj-(DD+ZZ))] = o;
                    } else {
                        float2 o = { v0, v1 };
                        *(float2*)&P.c4[(size_t)gi*DD + (gj-(DD+ZZ+HH))] = o;
                    }
                } else if (EPI==2){
                    const float invL = 1.0f/LSEQ;
                    const float* rel = P.aux0 + (LSEQ-1) - gi + gj;
                    float2 o = { laplace_(v0*invL + rel[0]),
                                 laplace_(v1*invL + rel[1]) };
                    *(float2*)&P.c0[(size_t)bz*P.strideC + (size_t)gi*P.ldc + gj] = o;
                } else if (EPI==3){
                    size_t idx = ((size_t)gi*8 + bz)*HH + gj;
                    float2 rr = *(const float2*)&P.aux0[idx];
                    float2 o = { v0*rr.x, v1*rr.y };
                    *(float2*)&P.c0[idx] = o;
                } else {
                    size_t idx = (size_t)gi*DD + gj;
                    float2 hb  = *(const float2*)&P.bias[gj];
                    float2 hx2 = *(const float2*)&P.aux0[idx];
                    float2 u2  = *(const float2*)&P.aux1[idx];
                    float2 x2  = *(const float2*)&P.aux2[idx];
                    float t0 = silu_(hx2.x + v0 + hb.x);
                    float t1 = silu_(hx2.y + v1 + hb.y);
                    float2 o = { x2.x + u2.x*(t0-x2.x), x2.y + u2.y*(t1-x2.y) };
                    *(float2*)&P.c0[idx] = o;
                }
            }
        }
    }
}

// ---------------- host ----------------
static const int GEMM_SMEM = 2*STAGEB;   // 81920

extern "C" void kernel_launch(void* const* d_in, const int* in_sizes, int n_in,
                              void* d_out, int out_size)
{
    const float* x      = (const float*)d_in[0];
    const float* delta  = (const float*)d_in[1];
    const float* alpha  = (const float*)d_in[2];
    const float* beta_e = (const float*)d_in[3];
    const float* gamma_e= (const float*)d_in[4];
    const float* omega  = (const float*)d_in[5];
    const float* v_w    = (const float*)d_in[6];
    const float* v_b    = (const float*)d_in[7];
    const float* mx_w   = (const float*)d_in[8];
    const float* mx_b   = (const float*)d_in[9];
    const float* h_w    = (const float*)d_in[10];
    const float* h_b    = (const float*)d_in[11];
    const float* qk_g   = (const float*)d_in[12];
    const float* qk_b   = (const float*)d_in[13];
    const float* rel    = (const float*)d_in[14];
    const float* ln_w   = (const float*)d_in[15];
    const float* ln_b   = (const float*)d_in[16];
    float* out = (float*)d_out;

    float *xn,*mx,*v,*vT,*u,*r,*hx,*qb,*kb,*attn,*hr,*vwT,*mxwT,*hwT;
    cudaGetSymbolAddress((void**)&xn,   g_xn);
    cudaGetSymbolAddress((void**)&mx,   g_mx);
    cudaGetSymbolAddress((void**)&v,    g_v);
    cudaGetSymbolAddress((void**)&vT,   g_vT);
    cudaGetSymbolAddress((void**)&u,    g_u);
    cudaGetSymbolAddress((void**)&r,    g_r);
    cudaGetSymbolAddress((void**)&hx,   g_hx);
    cudaGetSymbolAddress((void**)&qb,   g_q);
    cudaGetSymbolAddress((void**)&kb,   g_k);
    cudaGetSymbolAddress((void**)&attn, g_attn);
    cudaGetSymbolAddress((void**)&hr,   g_hr);
    cudaGetSymbolAddress((void**)&vwT,  g_vwT);
    cudaGetSymbolAddress((void**)&mxwT, g_mxwT);
    cudaGetSymbolAddress((void**)&hwT,  g_hwT);

    cudaFuncSetAttribute(gemm_mma<0>, cudaFuncAttributeMaxDynamicSharedMemorySize, GEMM_SMEM);
    cudaFuncSetAttribute(gemm_mma<1>, cudaFuncAttributeMaxDynamicSharedMemorySize, GEMM_SMEM);
    cudaFuncSetAttribute(gemm_mma<2>, cudaFuncAttributeMaxDynamicSharedMemorySize, GEMM_SMEM);
    cudaFuncSetAttribute(gemm_mma<3>, cudaFuncAttributeMaxDynamicSharedMemorySize, GEMM_SMEM);
    cudaFuncSetAttribute(gemm_mma<4>, cudaFuncAttributeMaxDynamicSharedMemorySize, GEMM_SMEM);

    dim3 tb(32,8);

    // weight transposes -> [N,K] K-major operands
    tr_w<<<dim3(HH/32,  DD/32), tb>>>(v_w,  vwT,  DD, HH);
    tr_w<<<dim3(NBASE/32, DD/32), tb>>>(mx_w, mxwT, DD, NBASE);
    tr_w<<<dim3(DD/32,  HH/32), tb>>>(h_w,  hwT,  HH, DD);

    // 1) layernorm
    ln_kernel<<<MROWS, 256>>>(x, ln_w, ln_b, xn);

    // 2) EMA
    ema_kernel<<<(BB*DD)/256, 256>>>(xn, delta, alpha, beta_e, gamma_e, omega, mx);

    // 3) v = silu(xn @ v_w + v_b)
    {
        EpiP P = {}; P.c0 = v; P.bias = v_b; P.ldc = HH;
        gemm_mma<0><<<dim3(HH/128, MROWS/128, 1), 256, GEMM_SMEM>>>(xn, vwT, DD, DD, DD, 0, 0, P);
    }
    tr_v<<<dim3(HH/32, LSEQ/32, BB), tb>>>(v, vT);

    // 4) base GEMM + split epilogue
    {
        EpiP P = {}; P.c0=u; P.c1=qb; P.c2=kb; P.c3=r; P.c4=hx;
        P.bias=mx_b; P.aux0=qk_g; P.aux1=qk_b;
        gemm_mma<1><<<dim3(NBASE/128, MROWS/128, 1), 256, GEMM_SMEM>>>(mx, mxwT, DD, DD, DD, 0, 0, P);
    }
    // 5) attn = laplace(q@k^T/L + bias)
    {
        EpiP P = {}; P.c0 = attn; P.aux0 = rel; P.ldc = LSEQ;
        P.strideC = (long)LSEQ*LSEQ;
        gemm_mma<2><<<dim3(LSEQ/128, LSEQ/128, BB), 256, GEMM_SMEM>>>(
            qb, kb, ZZ, ZZ, ZZ, (long)LSEQ*ZZ, (long)LSEQ*ZZ, P);
    }
    // 6) hr = (attn @ vb) * r, stored (L,B,H)
    {
        EpiP P = {}; P.c0 = hr; P.aux0 = r;
        gemm_mma<3><<<dim3(HH/128, LSEQ/128, BB), 256, GEMM_SMEM>>>(
            attn, vT, LSEQ, LSEQ, LSEQ, (long)LSEQ*LSEQ, (long)HH*LSEQ, P);
    }
    // 7) out = x + u*(silu(hx + hr@h_w + h_b) - x)
    {
        EpiP P = {}; P.c0 = out; P.bias = h_b; P.aux0 = hx; P.aux1 = u; P.aux2 = x;
        gemm_mma<4><<<dim3(DD/128, MROWS/128, 1), 256, GEMM_SMEM>>>(hr, hwT, HH, HH, HH, 0, 0, P);
    }
}

// round 4
// speedup vs baseline: 2.8604x; 1.4381x over previous
#include <cuda_runtime.h>
#include <cuda_bf16.h>
#include <math.h>
#include <stdint.h>

// ---------------- problem constants ----------------
#define LSEQ 2048
#define BB   8
#define DD   1024
#define ZZ   128
#define HH   2048
#define NN   16
#define MROWS (LSEQ*BB)           // 16384
#define NBASE (ZZ+HH+2*DD)        // 4224

typedef __nv_bfloat16 bf16;

// ---------------- scratch ----------------
// fp32
__device__ float g_xn [(size_t)MROWS*DD];
__device__ float g_v  [(size_t)MROWS*HH];
__device__ float g_u  [(size_t)MROWS*DD];
__device__ float g_r  [(size_t)MROWS*HH];
__device__ float g_hx [(size_t)MROWS*DD];
// bf16 hi/lo operand pairs
__device__ bf16 g_xnh[(size_t)MROWS*DD],   g_xnl[(size_t)MROWS*DD];
__device__ bf16 g_mxh[(size_t)MROWS*DD],   g_mxl[(size_t)MROWS*DD];
__device__ bf16 g_vwh[(size_t)HH*DD],      g_vwl[(size_t)HH*DD];
__device__ bf16 g_mxwh[(size_t)NBASE*DD],  g_mxwl[(size_t)NBASE*DD];
__device__ bf16 g_hwh[(size_t)DD*HH],      g_hwl[(size_t)DD*HH];
__device__ bf16 g_qh [(size_t)BB*LSEQ*ZZ], g_ql [(size_t)BB*LSEQ*ZZ];
__device__ bf16 g_kh [(size_t)BB*LSEQ*ZZ], g_kl [(size_t)BB*LSEQ*ZZ];
__device__ bf16 g_ath[(size_t)BB*LSEQ*LSEQ], g_atl[(size_t)BB*LSEQ*LSEQ];
__device__ bf16 g_vTh[(size_t)BB*HH*LSEQ], g_vTl[(size_t)BB*HH*LSEQ];
__device__ bf16 g_hrh[(size_t)MROWS*HH],   g_hrl[(size_t)MROWS*HH];

// ---------------- math helpers ----------------
__device__ __forceinline__ float sigm_(float x){ return 1.f/(1.f+expf(-x)); }
__device__ __forceinline__ float silu_(float x){ return x/(1.f+expf(-x)); }
__device__ __forceinline__ float laplace_(float x){
    const float inv = (float)(1.0/(0.282095*1.4142135623730951));
    return 0.5f*(1.f + erff((x - 0.707107f) * inv));
}
__device__ __forceinline__ uint32_t sm_u32(const void* p){
    uint32_t a;
    asm("{ .reg .u64 t; cvta.to.shared.u64 t, %1; cvt.u32.u64 %0, t; }" : "=r"(a) : "l"(p));
    return a;
}
__device__ __forceinline__ void ldm4(uint32_t* r, uint32_t addr){
    asm volatile("ldmatrix.sync.aligned.m8n8.x4.shared.b16 {%0,%1,%2,%3}, [%4];"
        : "=r"(r[0]),"=r"(r[1]),"=r"(r[2]),"=r"(r[3]) : "r"(addr));
}
__device__ __forceinline__ void mma16816(float* c, const uint32_t* a, uint32_t b0, uint32_t b1){
    asm volatile("mma.sync.aligned.m16n8k16.row.col.f32.bf16.bf16.f32 "
        "{%0,%1,%2,%3}, {%4,%5,%6,%7}, {%8,%9}, {%0,%1,%2,%3};"
        : "+f"(c[0]),"+f"(c[1]),"+f"(c[2]),"+f"(c[3])
        : "r"(a[0]),"r"(a[1]),"r"(a[2]),"r"(a[3]),"r"(b0),"r"(b1));
}
#define CPA(dst, src) asm volatile("cp.async.cg.shared.global [%0], [%1], 16;" :: "r"(dst), "l"(src))

__device__ __forceinline__ void split1(float v, bf16& h, bf16& l){
    h = __float2bfloat16(v);
    l = __float2bfloat16(v - __bfloat162float(h));
}
__device__ __forceinline__ void st_hilo2(bf16* H, bf16* L, size_t idx, float v0, float v1){
    bf16 h0,l0,h1,l1;
    split1(v0,h0,l0); split1(v1,h1,l1);
    __nv_bfloat162 th; th.x=h0; th.y=h1;
    __nv_bfloat162 tl; tl.x=l0; tl.y=l1;
    *(__nv_bfloat162*)(H+idx) = th;
    *(__nv_bfloat162*)(L+idx) = tl;
}
__device__ __forceinline__ void split4(float4 v, uint2& h, uint2& l){
    bf16 h0,h1,h2,h3,l0,l1,l2,l3;
    split1(v.x,h0,l0); split1(v.y,h1,l1); split1(v.z,h2,l2); split1(v.w,h3,l3);
    h.x = (uint32_t)__bfloat16_as_ushort(h0) | ((uint32_t)__bfloat16_as_ushort(h1)<<16);
    h.y = (uint32_t)__bfloat16_as_ushort(h2) | ((uint32_t)__bfloat16_as_ushort(h3)<<16);
    l.x = (uint32_t)__bfloat16_as_ushort(l0) | ((uint32_t)__bfloat16_as_ushort(l1)<<16);
    l.y = (uint32_t)__bfloat16_as_ushort(l2) | ((uint32_t)__bfloat16_as_ushort(l3)<<16);
}

// ---------------- LayerNorm: fp32 out + hi/lo ----------------
__global__ __launch_bounds__(256) void ln_kernel(
    const float* __restrict__ x, const float* __restrict__ w,
    const float* __restrict__ b, float* __restrict__ out,
    bf16* __restrict__ oh, bf16* __restrict__ ol)
{
    long row = blockIdx.x;
    int tid = threadIdx.x;
    float4 v = ((const float4*)(x + row*DD))[tid];
    float s  = v.x+v.y+v.z+v.w;
    float ss = fmaf(v.x,v.x, fmaf(v.y,v.y, fmaf(v.z,v.z, v.w*v.w)));
    #pragma unroll
    for (int o=16;o>0;o>>=1){
        s  += __shfl_xor_sync(0xffffffffu, s, o);
        ss += __shfl_xor_sync(0xffffffffu, ss, o);
    }
    __shared__ float sh0[8], sh1[8];
    int wid = tid>>5, lane = tid&31;
    if (lane==0){ sh0[wid]=s; sh1[wid]=ss; }
    __syncthreads();
    float S=0.f, SS=0.f;
    #pragma unroll
    for (int i=0;i<8;i++){ S += sh0[i]; SS += sh1[i]; }
    float mu  = S*(1.f/DD);
    float var = SS*(1.f/DD) - mu*mu;
    float inv = rsqrtf(var + 1e-5f);
    float4 wv = ((const float4*)w)[tid];
    float4 bv = ((const float4*)b)[tid];
    float4 o;
    o.x = (v.x-mu)*inv*wv.x + bv.x;
    o.y = (v.y-mu)*inv*wv.y + bv.y;
    o.z = (v.z-mu)*inv*wv.z + bv.z;
    o.w = (v.w-mu)*inv*wv.w + bv.w;
    ((float4*)(out + row*DD))[tid] = o;
    uint2 h,l; split4(o,h,l);
    *(uint2*)(oh + row*DD + tid*4) = h;
    *(uint2*)(ol + row*DD + tid*4) = l;
}

// ---------------- EMA -> mx hi/lo ----------------
__global__ __launch_bounds__(256) void ema_kernel(
    const float* __restrict__ xn,
    const float* __restrict__ delta, const float* __restrict__ alpha,
    const float* __restrict__ beta_e, const float* __restrict__ gamma_e,
    const float* __restrict__ omega,
    bf16* __restrict__ mh, bf16* __restrict__ ml)
{
    int gid = blockIdx.x*blockDim.x + threadIdx.x;   // b*1024+d
    int d = gid & (DD-1);
    float q[NN], pb[NN], g[NN], s[NN];
    #pragma unroll
    for (int n=0;n<NN;n++){
        float de = delta[d*NN+n];
        float p  = sigm_(de);
        q[n]  = 1.f - p*sigm_(alpha[d*NN+n]);
        pb[n] = p*beta_e[d*NN+n];
        g[n]  = gamma_e[d*NN+n]*0.25f;
        s[n]  = 0.f;
    }
    float om = omega[d];
    const float* xp = xn + gid;
    for (int l0=0; l0<LSEQ; l0+=8){
        float xv[8];
        #pragma unroll
        for (int i=0;i<8;i++) xv[i] = xp[(size_t)(l0+i)*(BB*DD)];
        #pragma unroll
        for (int i=0;i<8;i++){
            float xc = xv[i];
            float a0=0.f,a1=0.f,a2=0.f,a3=0.f;
            #pragma unroll
            for (int n=0;n<NN;n+=4){
                s[n]   = fmaf(q[n],   s[n],   pb[n]*xc);
                s[n+1] = fmaf(q[n+1], s[n+1], pb[n+1]*xc);
                s[n+2] = fmaf(q[n+2], s[n+2], pb[n+2]*xc);
                s[n+3] = fmaf(q[n+3], s[n+3], pb[n+3]*xc);
                a0 = fmaf(g[n],   s[n],   a0);
                a1 = fmaf(g[n+1], s[n+1], a1);
                a2 = fmaf(g[n+2], s[n+2], a2);
                a3 = fmaf(g[n+3], s[n+3], a3);
            }
            float y = silu_((a0+a1)+(a2+a3) + om*xc);
            bf16 hh,ll; split1(y,hh,ll);
            size_t idx = (size_t)(l0+i)*(BB*DD) + gid;
            mh[idx]=hh; ml[idx]=ll;
        }
    }
}

// ---------------- transposes (fp32 in -> bf16 hi/lo out) ----------------
__global__ __launch_bounds__(256) void tr_w(const float* __restrict__ in,
                                            bf16* __restrict__ oh, bf16* __restrict__ ol,
                                            int R, int C)
{
    __shared__ float t[32][33];
    int c0 = blockIdx.x*32, r0 = blockIdx.y*32;
    int tx = threadIdx.x, ty = threadIdx.y;
    #pragma unroll
    for (int k=0;k<4;k++)
        t[ty+8*k][tx] = in[(size_t)(r0+ty+8*k)*C + c0+tx];
    __syncthreads();
    #pragma unroll
    for (int k=0;k<4;k++){
        float v = t[tx][ty+8*k];
        bf16 hh,ll; split1(v,hh,ll);
        size_t idx = (size_t)(c0+ty+8*k)*R + r0+tx;
        oh[idx]=hh; ol[idx]=ll;
    }
}

__global__ __launch_bounds__(256) void tr_v(const float* __restrict__ v,
                                            bf16* __restrict__ oh, bf16* __restrict__ ol)
{
    __shared__ float t[32][33];
    int h0 = blockIdx.x*32, l0 = blockIdx.y*32, b = blockIdx.z;
    int tx = threadIdx.x, ty = threadIdx.y;
    #pragma unroll
    for (int k=0;k<4;k++)
        t[ty+8*k][tx] = v[((size_t)(l0+ty+8*k)*8 + b)*HH + h0+tx];
    __syncthreads();
    #pragma unroll
    for (int k=0;k<4;k++){
        float vv = t[tx][ty+8*k];
        bf16 hh,ll; split1(vv,hh,ll);
        size_t idx = (size_t)b*HH*LSEQ + (size_t)(h0+ty+8*k)*LSEQ + l0+tx;
        oh[idx]=hh; ol[idx]=ll;
    }
}

// ---------------- GEMM: cp.async + ldmatrix + 3xHMMA, 128x128x32, 3 stages ----------------
struct EpiP {
    float* f0; float* f1; float* f2;
    bf16* h0; bf16* h1; bf16* h2; bf16* h3;
    const float* bias; const float* aux0; const float* aux1; const float* aux2;
    long strideC; int ldc;
};

#define STG 32768

template<int EPI>
__global__ __launch_bounds__(256,2) void gemm_mma(
    const bf16* __restrict__ Ahg, const bf16* __restrict__ Alg,
    const bf16* __restrict__ Bhg, const bf16* __restrict__ Blg,
    int lda, int ldb, int K, long sA, long sB, EpiP P)
{
    extern __shared__ char smch[];
    const uint32_t smb = sm_u32(smch);
    const int tid = threadIdx.x;
    const int w = tid>>5, lane = tid&31;
    const int m0 = blockIdx.y*128, n0 = blockIdx.x*128, bz = blockIdx.z;
    Ahg += (size_t)bz*sA; Alg += (size_t)bz*sA;
    Bhg += (size_t)bz*sB; Blg += (size_t)bz*sB;
    const int mw = (w&1)*64, nw = (w>>1)*32;

    // staging: thread -> row r (0..127), granules g0,g0+1 (16B each) of all 4 tiles
    const int r  = tid>>1;
    const int g0 = (tid&1)*2;
    const int sw = (r>>1)&3;
    const uint32_t d0 = (uint32_t)(r*64 + ((g0      ^ sw)<<4));
    const uint32_t d1 = (uint32_t)(r*64 + (((g0+1)  ^ sw)<<4));
    const bf16* sAh = Ahg + (size_t)(m0+r)*lda + g0*8;
    const bf16* sAl = Alg + (size_t)(m0+r)*lda + g0*8;
    const bf16* sBh = Bhg + (size_t)(n0+r)*ldb + g0*8;
    const bf16* sBl = Blg + (size_t)(n0+r)*ldb + g0*8;

    auto issue = [&](int kt){
        uint32_t sb = smb + (uint32_t)(kt%3)*STG;
        const bf16* a0 = sAh + (size_t)kt*32;
        const bf16* a1 = sAl + (size_t)kt*32;
        const bf16* b0 = sBh + (size_t)kt*32;
        const bf16* b1 = sBl + (size_t)kt*32;
        CPA(sb+d0,         a0); CPA(sb+d1,         a0+8);
        CPA(sb+8192+d0,    a1); CPA(sb+8192+d1,    a1+8);
        CPA(sb+16384+d0,   b0); CPA(sb+16384+d1,   b0+8);
        CPA(sb+24576+d0,   b1); CPA(sb+24576+d1,   b1+8);
        asm volatile("cp.async.commit_group;");
    };

    // ldmatrix lane geometry
    const int ra   = lane&15;
    const int la16 = lane>>4;
    const int swA  = ((mw + ra)>>1)&3;
    const int rb   = (lane&7) + ((lane>>4)&1)*8;
    const int lb16 = (lane>>3)&1;
    const int swB  = ((nw + rb)>>1)&3;

    float acc[4][4][4];
    #pragma unroll
    for (int a=0;a<4;a++)
        #pragma unroll
        for (int n=0;n<4;n++)
            #pragma unroll
            for (int i=0;i<4;i++) acc[a][n][i]=0.f;

    const int nk = K/32;
    issue(0); issue(1);

    for (int kt=0; kt<nk; kt++){
        if (kt == nk-1) asm volatile("cp.async.wait_group 0;");
        else            asm volatile("cp.async.wait_group 1;");
        __syncthreads();
        if (kt+2 < nk) issue(kt+2);

        const uint32_t sb = smb + (uint32_t)(kt%3)*STG;
        #pragma unroll
        for (int ks=0; ks<2; ks++){
            uint32_t bh[2][4], bl[2][4];
            #pragma unroll
            for (int p=0;p<2;p++){
                uint32_t bd = sb + 16384u +
                    (uint32_t)((nw+rb+p*16)*64 + (((ks*2+lb16)^swB)<<4));
                ldm4(bh[p], bd);
                ldm4(bl[p], bd + 8192);
            }
            #pragma unroll
            for (int a=0;a<4;a++){
                uint32_t ah[4], al[4];
                uint32_t ad = sb +
                    (uint32_t)((mw+ra+a*16)*64 + (((ks*2+la16)^swA)<<4));
                ldm4(ah, ad);
                ldm4(al, ad + 8192);
                #pragma unroll
                for (int n=0;n<4;n++){
                    const int p=n>>1, q=(n&1)*2;
                    mma16816(acc[a][n], ah, bh[p][q], bh[p][q+1]);
                    mma16816(acc[a][n], al, bh[p][q], bh[p][q+1]);
                    mma16816(acc[a][n], ah, bl[p][q], bl[p][q+1]);
                }
            }
        }
        __syncthreads();
    }

    // ---------------- epilogue ----------------
    #pragma unroll
    for (int a=0;a<4;a++){
        #pragma unroll
        for (int n=0;n<4;n++){
            const int gj = n0 + nw + n*8 + (lane&3)*2;
            #pragma unroll
            for (int half=0; half<2; half++){
                const int gi = m0 + mw + a*16 + (lane>>2) + half*8;
                float v0 = acc[a][n][half*2+0];
                float v1 = acc[a][n][half*2+1];
                if (EPI==0){
                    float2 o = { silu_(v0 + P.bias[gj]), silu_(v1 + P.bias[gj+1]) };
                    *(float2*)&P.f0[(size_t)gi*P.ldc + gj] = o;
                } else if (EPI==1){
                    v0 += P.bias[gj]; v1 += P.bias[gj+1];
                    if (n0 < DD){
                        float2 o = { sigm_(v0), sigm_(v1) };
                        *(float2*)&P.f0[(size_t)gi*DD + gj] = o;
                    } else if (n0 < DD+ZZ){
                        int zi = gj - DD;
                        int l = gi>>3, b = gi&7;
                        size_t qi = ((size_t)b*LSEQ + l)*ZZ + zi;
                        float z0 = silu_(v0), z1 = silu_(v1);
                        float q0 = z0*P.aux0[zi]   + P.aux1[zi];
                        float q1 = z1*P.aux0[zi+1] + P.aux1[zi+1];
                        float k0 = z0*P.aux0[ZZ+zi]   + P.aux1[ZZ+zi];
                        float k1 = z1*P.aux0[ZZ+zi+1] + P.aux1[ZZ+zi+1];
                        st_hilo2(P.h0, P.h1, qi, q0, q1);
                        st_hilo2(P.h2, P.h3, qi, k0, k1);
                    } else if (n0 < DD+ZZ+HH){
                        float2 o = { silu_(v0), silu_(v1) };
                        *(float2*)&P.f1[(size_t)gi*HH + (gj-(DD+ZZ))] = o;
                    } else {
                        float2 o = { v0, v1 };
                        *(float2*)&P.f2[(size_t)gi*DD + (gj-(DD+ZZ+HH))] = o;
                    }
                } else if (EPI==2){
                    const float invL = 1.0f/LSEQ;
                    const float* rel = P.aux0 + (LSEQ-1) - gi + gj;
                    float o0 = laplace_(v0*invL + rel[0]);
                    float o1 = laplace_(v1*invL + rel[1]);
                    st_hilo2(P.h0, P.h1,
                             (size_t)bz*P.strideC + (size_t)gi*P.ldc + gj, o0, o1);
                } else if (EPI==3){
                    size_t idx = ((size_t)gi*8 + bz)*HH + gj;
                    float2 rr = *(const float2*)&P.aux0[idx];
                    st_hilo2(P.h0, P.h1, idx, v0*rr.x, v1*rr.y);
                } else {
                    size_t idx = (size_t)gi*DD + gj;
                    float2 hb  = *(const float2*)&P.bias[gj];
                    float2 hx2 = *(const float2*)&P.aux0[idx];
                    float2 u2  = *(const float2*)&P.aux1[idx];
                    float2 x2  = *(const float2*)&P.aux2[idx];
                    float t0 = silu_(hx2.x + v0 + hb.x);
                    float t1 = silu_(hx2.y + v1 + hb.y);
                    float2 o = { x2.x + u2.x*(t0-x2.x), x2.y + u2.y*(t1-x2.y) };
                    *(float2*)&P.f0[idx] = o;
                }
            }
        }
    }
}

// ---------------- host ----------------
static const int GEMM_SMEM = 3*STG;   // 98304

extern "C" void kernel_launch(void* const* d_in, const int* in_sizes, int n_in,
                              void* d_out, int out_size)
{
    const float* x      = (const float*)d_in[0];
    const float* delta  = (const float*)d_in[1];
    const float* alpha  = (const float*)d_in[2];
    const float* beta_e = (const float*)d_in[3];
    const float* gamma_e= (const float*)d_in[4];
    const float* omega  = (const float*)d_in[5];
    const float* v_w    = (const float*)d_in[6];
    const float* v_b    = (const float*)d_in[7];
    const float* mx_w   = (const float*)d_in[8];
    const float* mx_b   = (const float*)d_in[9];
    const float* h_w    = (const float*)d_in[10];
    const float* h_b    = (const float*)d_in[11];
    const float* qk_g   = (const float*)d_in[12];
    const float* qk_b   = (const float*)d_in[13];
    const float* rel    = (const float*)d_in[14];
    const float* ln_w   = (const float*)d_in[15];
    const float* ln_b   = (const float*)d_in[16];
    float* out = (float*)d_out;

    float *xn,*v,*u,*r,*hx;
    bf16 *xnh,*xnl,*mxh,*mxl,*vwh,*vwl,*mxwh,*mxwl,*hwh,*hwl;
    bf16 *qh,*ql,*kh,*kl,*ath,*atl,*vTh,*vTl,*hrh,*hrl;
    cudaGetSymbolAddress((void**)&xn, g_xn);
    cudaGetSymbolAddress((void**)&v,  g_v);
    cudaGetSymbolAddress((void**)&u,  g_u);
    cudaGetSymbolAddress((void**)&r,  g_r);
    cudaGetSymbolAddress((void**)&hx, g_hx);
    cudaGetSymbolAddress((void**)&xnh, g_xnh);  cudaGetSymbolAddress((void**)&xnl, g_xnl);
    cudaGetSymbolAddress((void**)&mxh, g_mxh);  cudaGetSymbolAddress((void**)&mxl, g_mxl);
    cudaGetSymbolAddress((void**)&vwh, g_vwh);  cudaGetSymbolAddress((void**)&vwl, g_vwl);
    cudaGetSymbolAddress((void**)&mxwh,g_mxwh); cudaGetSymbolAddress((void**)&mxwl,g_mxwl);
    cudaGetSymbolAddress((void**)&hwh, g_hwh);  cudaGetSymbolAddress((void**)&hwl, g_hwl);
    cudaGetSymbolAddress((void**)&qh,  g_qh);   cudaGetSymbolAddress((void**)&ql,  g_ql);
    cudaGetSymbolAddress((void**)&kh,  g_kh);   cudaGetSymbolAddress((void**)&kl,  g_kl);
    cudaGetSymbolAddress((void**)&ath, g_ath);  cudaGetSymbolAddress((void**)&atl, g_atl);
    cudaGetSymbolAddress((void**)&vTh, g_vTh);  cudaGetSymbolAddress((void**)&vTl, g_vTl);
    cudaGetSymbolAddress((void**)&hrh, g_hrh);  cudaGetSymbolAddress((void**)&hrl, g_hrl);

    cudaFuncSetAttribute(gemm_mma<0>, cudaFuncAttributeMaxDynamicSharedMemorySize, GEMM_SMEM);
    cudaFuncSetAttribute(gemm_mma<1>, cudaFuncAttributeMaxDynamicSharedMemorySize, GEMM_SMEM);
    cudaFuncSetAttribute(gemm_mma<2>, cudaFuncAttributeMaxDynamicSharedMemorySize, GEMM_SMEM);
    cudaFuncSetAttribute(gemm_mma<3>, cudaFuncAttributeMaxDynamicSharedMemorySize, GEMM_SMEM);
    cudaFuncSetAttribute(gemm_mma<4>, cudaFuncAttributeMaxDynamicSharedMemorySize, GEMM_SMEM);

    dim3 tb(32,8);

    // weight transposes -> bf16 hi/lo [N,K]
    tr_w<<<dim3(HH/32,  DD/32), tb>>>(v_w,  vwh, vwl, DD, HH);
    tr_w<<<dim3(NBASE/32, DD/32), tb>>>(mx_w, mxwh, mxwl, DD, NBASE);
    tr_w<<<dim3(DD/32,  HH/32), tb>>>(h_w,  hwh, hwl, HH, DD);

    // 1) layernorm (fp32 + hi/lo)
    ln_kernel<<<MROWS, 256>>>(x, ln_w, ln_b, xn, xnh, xnl);

    // 2) EMA -> mx hi/lo
    ema_kernel<<<(BB*DD)/256, 256>>>(xn, delta, alpha, beta_e, gamma_e, omega, mxh, mxl);

    // 3) v = silu(xn @ v_w + v_b)   fp32 out
    {
        EpiP P = {}; P.f0 = v; P.bias = v_b; P.ldc = HH;
        gemm_mma<0><<<dim3(HH/128, MROWS/128, 1), 256, GEMM_SMEM>>>(
            xnh, xnl, vwh, vwl, DD, DD, DD, 0, 0, P);
    }
    tr_v<<<dim3(HH/32, LSEQ/32, BB), tb>>>(v, vTh, vTl);

    // 4) base GEMM + split epilogue
    {
        EpiP P = {}; P.f0=u; P.f1=r; P.f2=hx;
        P.h0=qh; P.h1=ql; P.h2=kh; P.h3=kl;
        P.bias=mx_b; P.aux0=qk_g; P.aux1=qk_b;
        gemm_mma<1><<<dim3(NBASE/128, MROWS/128, 1), 256, GEMM_SMEM>>>(
            mxh, mxl, mxwh, mxwl, DD, DD, DD, 0, 0, P);
    }
    // 5) attn = laplace(q@k^T/L + bias) -> hi/lo
    {
        EpiP P = {}; P.h0 = ath; P.h1 = atl; P.aux0 = rel; P.ldc = LSEQ;
        P.strideC = (long)LSEQ*LSEQ;
        gemm_mma<2><<<dim3(LSEQ/128, LSEQ/128, BB), 256, GEMM_SMEM>>>(
            qh, ql, kh, kl, ZZ, ZZ, ZZ, (long)LSEQ*ZZ, (long)LSEQ*ZZ, P);
    }
    // 6) hr = (attn @ vb) * r -> hi/lo (L,B,H)
    {
        EpiP P = {}; P.h0 = hrh; P.h1 = hrl; P.aux0 = r;
        gemm_mma<3><<<dim3(HH/128, LSEQ/128, BB), 256, GEMM_SMEM>>>(
            ath, atl, vTh, vTl, LSEQ, LSEQ, LSEQ, (long)LSEQ*LSEQ, (long)HH*LSEQ, P);
    }
    // 7) out = x + u*(silu(hx + hr@h_w + h_b) - x)
    {
        EpiP P = {}; P.f0 = out; P.bias = h_b; P.aux0 = hx; P.aux1 = u; P.aux2 = x;
        gemm_mma<4><<<dim3(DD/128, MROWS/128, 1), 256, GEMM_SMEM>>>(
            hrh, hrl, hwh, hwl, HH, HH, HH, 0, 0, P);
    }
}

// round 5
// speedup vs baseline: 3.8850x; 1.3582x over previous
#include <cuda_runtime.h>
#include <cuda_fp16.h>
#include <math.h>
#include <stdint.h>

// ---------------- problem constants ----------------
#define LSEQ 2048
#define BB   8
#define DD   1024
#define ZZ   128
#define HH   2048
#define NN   16
#define MROWS (LSEQ*BB)           // 16384
#define NBASE (ZZ+HH+2*DD)        // 4224

typedef __half h16;

// ---------------- scratch ----------------
// fp32
__device__ float g_xn [(size_t)MROWS*DD];
__device__ float g_v  [(size_t)MROWS*HH];
__device__ float g_u  [(size_t)MROWS*DD];
__device__ float g_r  [(size_t)MROWS*HH];
__device__ float g_hx [(size_t)MROWS*DD];
// A-side fp16 hi/lo pairs
__device__ h16 g_xnh[(size_t)MROWS*DD],   g_xnl[(size_t)MROWS*DD];
__device__ h16 g_mxh[(size_t)MROWS*DD],   g_mxl[(size_t)MROWS*DD];
__device__ h16 g_qh [(size_t)BB*LSEQ*ZZ], g_ql [(size_t)BB*LSEQ*ZZ];
__device__ h16 g_ath[(size_t)BB*LSEQ*LSEQ], g_atl[(size_t)BB*LSEQ*LSEQ];
__device__ h16 g_hrh[(size_t)MROWS*HH],   g_hrl[(size_t)MROWS*HH];
// B-side fp16 single
__device__ h16 g_vw [(size_t)HH*DD];
__device__ h16 g_mxw[(size_t)NBASE*DD];
__device__ h16 g_hw [(size_t)DD*HH];
__device__ h16 g_k  [(size_t)BB*LSEQ*ZZ];
__device__ h16 g_vT [(size_t)BB*HH*LSEQ];

// ---------------- math helpers ----------------
__device__ __forceinline__ float sigm_(float x){ return 1.f/(1.f+expf(-x)); }
__device__ __forceinline__ float silu_(float x){ return x/(1.f+expf(-x)); }
__device__ __forceinline__ float laplace_(float x){
    const float inv = (float)(1.0/(0.282095*1.4142135623730951));
    return 0.5f*(1.f + erff((x - 0.707107f) * inv));
}
__device__ __forceinline__ uint32_t sm_u32(const void* p){
    uint32_t a;
    asm("{ .reg .u64 t; cvta.to.shared.u64 t, %1; cvt.u32.u64 %0, t; }" : "=r"(a) : "l"(p));
    return a;
}
__device__ __forceinline__ void ldm4(uint32_t* r, uint32_t addr){
    asm volatile("ldmatrix.sync.aligned.m8n8.x4.shared.b16 {%0,%1,%2,%3}, [%4];"
        : "=r"(r[0]),"=r"(r[1]),"=r"(r[2]),"=r"(r[3]) : "r"(addr));
}
__device__ __forceinline__ void mma16816(float* c, const uint32_t* a, uint32_t b0, uint32_t b1){
    asm volatile("mma.sync.aligned.m16n8k16.row.col.f32.f16.f16.f32 "
        "{%0,%1,%2,%3}, {%4,%5,%6,%7}, {%8,%9}, {%0,%1,%2,%3};"
        : "+f"(c[0]),"+f"(c[1]),"+f"(c[2]),"+f"(c[3])
        : "r"(a[0]),"r"(a[1]),"r"(a[2]),"r"(a[3]),"r"(b0),"r"(b1));
}
#define CPA(dst, src) asm volatile("cp.async.cg.shared.global [%0], [%1], 16;" :: "r"(dst), "l"(src))

__device__ __forceinline__ void split1(float v, h16& h, h16& l){
    h = __float2half(v);
    l = __float2half(v - __half2float(h));
}
__device__ __forceinline__ void st_hilo2(h16* H, h16* L, size_t idx, float v0, float v1){
    h16 h0,l0,h1,l1;
    split1(v0,h0,l0); split1(v1,h1,l1);
    __half2 th; th.x=h0; th.y=h1;
    __half2 tl; tl.x=l0; tl.y=l1;
    *(__half2*)(H+idx) = th;
    *(__half2*)(L+idx) = tl;
}
__device__ __forceinline__ void st2(h16* H, size_t idx, float v0, float v1){
    __half2 t; t.x=__float2half(v0); t.y=__float2half(v1);
    *(__half2*)(H+idx) = t;
}
__device__ __forceinline__ void split4(float4 v, uint2& h, uint2& l){
    h16 h0,h1,h2,h3,l0,l1,l2,l3;
    split1(v.x,h0,l0); split1(v.y,h1,l1); split1(v.z,h2,l2); split1(v.w,h3,l3);
    h.x = (uint32_t)__half_as_ushort(h0) | ((uint32_t)__half_as_ushort(h1)<<16);
    h.y = (uint32_t)__half_as_ushort(h2) | ((uint32_t)__half_as_ushort(h3)<<16);
    l.x = (uint32_t)__half_as_ushort(l0) | ((uint32_t)__half_as_ushort(l1)<<16);
    l.y = (uint32_t)__half_as_ushort(l2) | ((uint32_t)__half_as_ushort(l3)<<16);
}

// ---------------- LayerNorm: fp32 out + fp16 hi/lo ----------------
__global__ __launch_bounds__(256) void ln_kernel(
    const float* __restrict__ x, const float* __restrict__ w,
    const float* __restrict__ b, float* __restrict__ out,
    h16* __restrict__ oh, h16* __restrict__ ol)
{
    long row = blockIdx.x;
    int tid = threadIdx.x;
    float4 v = ((const float4*)(x + row*DD))[tid];
    float s  = v.x+v.y+v.z+v.w;
    float ss = fmaf(v.x,v.x, fmaf(v.y,v.y, fmaf(v.z,v.z, v.w*v.w)));
    #pragma unroll
    for (int o=16;o>0;o>>=1){
        s  += __shfl_xor_sync(0xffffffffu, s, o);
        ss += __shfl_xor_sync(0xffffffffu, ss, o);
    }
    __shared__ float sh0[8], sh1[8];
    int wid = tid>>5, lane = tid&31;
    if (lane==0){ sh0[wid]=s; sh1[wid]=ss; }
    __syncthreads();
    float S=0.f, SS=0.f;
    #pragma unroll
    for (int i=0;i<8;i++){ S += sh0[i]; SS += sh1[i]; }
    float mu  = S*(1.f/DD);
    float var = SS*(1.f/DD) - mu*mu;
    float inv = rsqrtf(var + 1e-5f);
    float4 wv = ((const float4*)w)[tid];
    float4 bv = ((const float4*)b)[tid];
    float4 o;
    o.x = (v.x-mu)*inv*wv.x + bv.x;
    o.y = (v.y-mu)*inv*wv.y + bv.y;
    o.z = (v.z-mu)*inv*wv.z + bv.z;
    o.w = (v.w-mu)*inv*wv.w + bv.w;
    ((float4*)(out + row*DD))[tid] = o;
    uint2 h,l; split4(o,h,l);
    *(uint2*)(oh + row*DD + tid*4) = h;
    *(uint2*)(ol + row*DD + tid*4) = l;
}

// ---------------- EMA -> mx hi/lo ----------------
__global__ __launch_bounds__(256) void ema_kernel(
    const float* __restrict__ xn,
    const float* __restrict__ delta, const float* __restrict__ alpha,
    const float* __restrict__ beta_e, const float* __restrict__ gamma_e,
    const float* __restrict__ omega,
    h16* __restrict__ mh, h16* __restrict__ ml)
{
    int gid = blockIdx.x*blockDim.x + threadIdx.x;   // b*1024+d
    int d = gid & (DD-1);
    float q[NN], pb[NN], g[NN], s[NN];
    #pragma unroll
    for (int n=0;n<NN;n++){
        float de = delta[d*NN+n];
        float p  = sigm_(de);
        q[n]  = 1.f - p*sigm_(alpha[d*NN+n]);
        pb[n] = p*beta_e[d*NN+n];
        g[n]  = gamma_e[d*NN+n]*0.25f;
        s[n]  = 0.f;
    }
    float om = omega[d];
    const float* xp = xn + gid;
    for (int l0=0; l0<LSEQ; l0+=8){
        float xv[8];
        #pragma unroll
        for (int i=0;i<8;i++) xv[i] = xp[(size_t)(l0+i)*(BB*DD)];
        #pragma unroll
        for (int i=0;i<8;i++){
            float xc = xv[i];
            float a0=0.f,a1=0.f,a2=0.f,a3=0.f;
            #pragma unroll
            for (int n=0;n<NN;n+=4){
                s[n]   = fmaf(q[n],   s[n],   pb[n]*xc);
                s[n+1] = fmaf(q[n+1], s[n+1], pb[n+1]*xc);
                s[n+2] = fmaf(q[n+2], s[n+2], pb[n+2]*xc);
                s[n+3] = fmaf(q[n+3], s[n+3], pb[n+3]*xc);
                a0 = fmaf(g[n],   s[n],   a0);
                a1 = fmaf(g[n+1], s[n+1], a1);
                a2 = fmaf(g[n+2], s[n+2], a2);
                a3 = fmaf(g[n+3], s[n+3], a3);
            }
            float y = silu_((a0+a1)+(a2+a3) + om*xc);
            h16 hh,ll; split1(y,hh,ll);
            size_t idx = (size_t)(l0+i)*(BB*DD) + gid;
            mh[idx]=hh; ml[idx]=ll;
        }
    }
}

// ---------------- transposes ----------------
// B-side weight transpose: fp32 in -> single fp16 out, out[c][r] = in[r][c]
__global__ __launch_bounds__(256) void tr_w(const float* __restrict__ in,
                                            h16* __restrict__ oh, int R, int C)
{
    __shared__ float t[32][33];
    int c0 = blockIdx.x*32, r0 = blockIdx.y*32;
    int tx = threadIdx.x, ty = threadIdx.y;
    #pragma unroll
    for (int k=0;k<4;k++)
        t[ty+8*k][tx] = in[(size_t)(r0+ty+8*k)*C + c0+tx];
    __syncthreads();
    #pragma unroll
    for (int k=0;k<4;k++)
        oh[(size_t)(c0+ty+8*k)*R + r0+tx] = __float2half(t[tx][ty+8*k]);
}

__global__ __launch_bounds__(256) void tr_v(const float* __restrict__ v,
                                            h16* __restrict__ oh)
{
    __shared__ float t[32][33];
    int h0 = blockIdx.x*32, l0 = blockIdx.y*32, b = blockIdx.z;
    int tx = threadIdx.x, ty = threadIdx.y;
    #pragma unroll
    for (int k=0;k<4;k++)
        t[ty+8*k][tx] = v[((size_t)(l0+ty+8*k)*8 + b)*HH + h0+tx];
    __syncthreads();
    #pragma unroll
    for (int k=0;k<4;k++)
        oh[(size_t)b*HH*LSEQ + (size_t)(h0+ty+8*k)*LSEQ + l0+tx] =
            __float2half(t[tx][ty+8*k]);
}

// ---------------- GEMM: cp.async + ldmatrix + 2xHMMA fp16, 128x128x32, 4 stages ----------------
struct EpiP {
    float* f0; float* f1; float* f2;
    h16* h0; h16* h1; h16* h2;
    const float* bias; const float* aux0; const float* aux1; const float* aux2;
    long strideC; int ldc;
};

#define STG 24576

template<int EPI>
__global__ __launch_bounds__(256,2) void gemm_mma(
    const h16* __restrict__ Ahg, const h16* __restrict__ Alg,
    const h16* __restrict__ Bhg,
    int lda, int ldb, int K, long sA, long sB, EpiP P)
{
    extern __shared__ char smch[];
    const uint32_t smb = sm_u32(smch);
    const int tid = threadIdx.x;
    const int w = tid>>5, lane = tid&31;
    const int m0 = blockIdx.y*128, n0 = blockIdx.x*128, bz = blockIdx.z;
    Ahg += (size_t)bz*sA; Alg += (size_t)bz*sA;
    Bhg += (size_t)bz*sB;
    const int mw = (w&1)*64, nw = (w>>1)*32;

    // staging: thread -> row r (0..127), granules g0,g0+1 (16B) of each tile
    const int r  = tid>>1;
    const int g0 = (tid&1)*2;
    const int sw = (r>>1)&3;
    const uint32_t d0 = (uint32_t)(r*64 + ((g0     ^ sw)<<4));
    const uint32_t d1 = (uint32_t)(r*64 + (((g0+1) ^ sw)<<4));
    const h16* sAh = Ahg + (size_t)(m0+r)*lda + g0*8;
    const h16* sAl = Alg + (size_t)(m0+r)*lda + g0*8;
    const h16* sBh = Bhg + (size_t)(n0+r)*ldb + g0*8;

    auto issue = [&](int kt){
        uint32_t sb = smb + (uint32_t)(kt&3)*STG;
        const h16* a0 = sAh + (size_t)kt*32;
        const h16* a1 = sAl + (size_t)kt*32;
        const h16* b0 = sBh + (size_t)kt*32;
        CPA(sb+d0,        a0); CPA(sb+d1,        a0+8);
        CPA(sb+8192+d0,   a1); CPA(sb+8192+d1,   a1+8);
        CPA(sb+16384+d0,  b0); CPA(sb+16384+d1,  b0+8);
        asm volatile("cp.async.commit_group;");
    };

    // ldmatrix lane geometry
    const int ra   = lane&15;
    const int la16 = lane>>4;
    const int swA  = ((mw + ra)>>1)&3;
    const int rb   = (lane&7) + ((lane>>4)&1)*8;
    const int lb16 = (lane>>3)&1;
    const int swB  = ((nw + rb)>>1)&3;

    float acc[4][4][4];
    #pragma unroll
    for (int a=0;a<4;a++)
        #pragma unroll
        for (int n=0;n<4;n++)
            #pragma unroll
            for (int i=0;i<4;i++) acc[a][n][i]=0.f;

    const int nk = K/32;
    issue(0); issue(1); issue(2);

    for (int kt=0; kt<nk; kt++){
        if (kt+2 < nk) asm volatile("cp.async.wait_group 2;");
        else           asm volatile("cp.async.wait_group 0;");
        __syncthreads();
        if (kt+3 < nk) issue(kt+3);

        const uint32_t sb = smb + (uint32_t)(kt&3)*STG;
        #pragma unroll
        for (int ks=0; ks<2; ks++){
            uint32_t bh[2][4];
            #pragma unroll
            for (int p=0;p<2;p++){
                uint32_t bd = sb + 16384u +
                    (uint32_t)((nw+rb+p*16)*64 + (((ks*2+lb16)^swB)<<4));
                ldm4(bh[p], bd);
            }
            #pragma unroll
            for (int a=0;a<4;a++){
                uint32_t ah[4], al[4];
                uint32_t ad = sb +
                    (uint32_t)((mw+ra+a*16)*64 + (((ks*2+la16)^swA)<<4));
                ldm4(ah, ad);
                ldm4(al, ad + 8192);
                #pragma unroll
                for (int n=0;n<4;n++){
                    const int p=n>>1, q=(n&1)*2;
                    mma16816(acc[a][n], ah, bh[p][q], bh[p][q+1]);
                    mma16816(acc[a][n], al, bh[p][q], bh[p][q+1]);
                }
            }
        }
        // no trailing __syncthreads: next iteration's barrier orders stage reuse
    }

    // ---------------- epilogue ----------------
    #pragma unroll
    for (int a=0;a<4;a++){
        #pragma unroll
        for (int n=0;n<4;n++){
            const int gj = n0 + nw + n*8 + (lane&3)*2;
            #pragma unroll
            for (int half=0; half<2; half++){
                const int gi = m0 + mw + a*16 + (lane>>2) + half*8;
                float v0 = acc[a][n][half*2+0];
                float v1 = acc[a][n][half*2+1];
                if (EPI==0){
                    float2 o = { silu_(v0 + P.bias[gj]), silu_(v1 + P.bias[gj+1]) };
                    *(float2*)&P.f0[(size_t)gi*P.ldc + gj] = o;
                } else if (EPI==1){
                    v0 += P.bias[gj]; v1 += P.bias[gj+1];
                    if (n0 < DD){
                        float2 o = { sigm_(v0), sigm_(v1) };
                        *(float2*)&P.f0[(size_t)gi*DD + gj] = o;
                    } else if (n0 < DD+ZZ){
                        int zi = gj - DD;
                        int l = gi>>3, b = gi&7;
                        size_t qi = ((size_t)b*LSEQ + l)*ZZ + zi;
                        float z0 = silu_(v0), z1 = silu_(v1);
                        float q0 = z0*P.aux0[zi]   + P.aux1[zi];
                        float q1 = z1*P.aux0[zi+1] + P.aux1[zi+1];
                        float k0 = z0*P.aux0[ZZ+zi]   + P.aux1[ZZ+zi];
                        float k1 = z1*P.aux0[ZZ+zi+1] + P.aux1[ZZ+zi+1];
                        st_hilo2(P.h0, P.h1, qi, q0, q1);   // q hi/lo (A-side)
                        st2(P.h2, qi, k0, k1);              // k single (B-side)
                    } else if (n0 < DD+ZZ+HH){
                        float2 o = { silu_(v0), silu_(v1) };
                        *(float2*)&P.f1[(size_t)gi*HH + (gj-(DD+ZZ))] = o;
                    } else {
                        float2 o = { v0, v1 };
                        *(float2*)&P.f2[(size_t)gi*DD + (gj-(DD+ZZ+HH))] = o;
                    }
                } else if (EPI==2){
                    const float invL = 1.0f/LSEQ;
                    const float* rel = P.aux0 + (LSEQ-1) - gi + gj;
                    float o0 = laplace_(v0*invL + rel[0]);
                    float o1 = laplace_(v1*invL + rel[1]);
                    st_hilo2(P.h0, P.h1,
                             (size_t)bz*P.strideC + (size_t)gi*P.ldc + gj, o0, o1);
                } else if (EPI==3){
                    size_t idx = ((size_t)gi*8 + bz)*HH + gj;
                    float2 rr = *(const float2*)&P.aux0[idx];
                    st_hilo2(P.h0, P.h1, idx, v0*rr.x, v1*rr.y);
                } else {
                    size_t idx = (size_t)gi*DD + gj;
                    float2 hb  = *(const float2*)&P.bias[gj];
                    float2 hx2 = *(const float2*)&P.aux0[idx];
                    float2 u2  = *(const float2*)&P.aux1[idx];
                    float2 x2  = *(const float2*)&P.aux2[idx];
                    float t0 = silu_(hx2.x + v0 + hb.x);
                    float t1 = silu_(hx2.y + v1 + hb.y);
                    float2 o = { x2.x + u2.x*(t0-x2.x), x2.y + u2.y*(t1-x2.y) };
                    *(float2*)&P.f0[idx] = o;
                }
            }
        }
    }
}

// ---------------- host ----------------
static const int GEMM_SMEM = 4*STG;   // 98304

extern "C" void kernel_launch(void* const* d_in, const int* in_sizes, int n_in,
                              void* d_out, int out_size)
{
    const float* x      = (const float*)d_in[0];
    const float* delta  = (const float*)d_in[1];
    const float* alpha  = (const float*)d_in[2];
    const float* beta_e = (const float*)d_in[3];
    const float* gamma_e= (const float*)d_in[4];
    const float* omega  = (const float*)d_in[5];
    const float* v_w    = (const float*)d_in[6];
    const float* v_b    = (const float*)d_in[7];
    const float* mx_w   = (const float*)d_in[8];
    const float* mx_b   = (const float*)d_in[9];
    const float* h_w    = (const float*)d_in[10];
    const float* h_b    = (const float*)d_in[11];
    const float* qk_g   = (const float*)d_in[12];
    const float* qk_b   = (const float*)d_in[13];
    const float* rel    = (const float*)d_in[14];
    const float* ln_w   = (const float*)d_in[15];
    const float* ln_b   = (const float*)d_in[16];
    float* out = (float*)d_out;

    float *xn,*v,*u,*r,*hx;
    h16 *xnh,*xnl,*mxh,*mxl,*qh,*ql,*ath,*atl,*hrh,*hrl;
    h16 *vw,*mxw,*hw,*kk,*vT;
    cudaGetSymbolAddress((void**)&xn, g_xn);
    cudaGetSymbolAddress((void**)&v,  g_v);
    cudaGetSymbolAddress((void**)&u,  g_u);
    cudaGetSymbolAddress((void**)&r,  g_r);
    cudaGetSymbolAddress((void**)&hx, g_hx);
    cudaGetSymbolAddress((void**)&xnh, g_xnh);  cudaGetSymbolAddress((void**)&xnl, g_xnl);
    cudaGetSymbolAddress((void**)&mxh, g_mxh);  cudaGetSymbolAddress((void**)&mxl, g_mxl);
    cudaGetSymbolAddress((void**)&qh,  g_qh);   cudaGetSymbolAddress((void**)&ql,  g_ql);
    cudaGetSymbolAddress((void**)&ath, g_ath);  cudaGetSymbolAddress((void**)&atl, g_atl);
    cudaGetSymbolAddress((void**)&hrh, g_hrh);  cudaGetSymbolAddress((void**)&hrl, g_hrl);
    cudaGetSymbolAddress((void**)&vw,  g_vw);
    cudaGetSymbolAddress((void**)&mxw, g_mxw);
    cudaGetSymbolAddress((void**)&hw,  g_hw);
    cudaGetSymbolAddress((void**)&kk,  g_k);
    cudaGetSymbolAddress((void**)&vT,  g_vT);

    cudaFuncSetAttribute(gemm_mma<0>, cudaFuncAttributeMaxDynamicSharedMemorySize, GEMM_SMEM);
    cudaFuncSetAttribute(gemm_mma<1>, cudaFuncAttributeMaxDynamicSharedMemorySize, GEMM_SMEM);
    cudaFuncSetAttribute(gemm_mma<2>, cudaFuncAttributeMaxDynamicSharedMemorySize, GEMM_SMEM);
    cudaFuncSetAttribute(gemm_mma<3>, cudaFuncAttributeMaxDynamicSharedMemorySize, GEMM_SMEM);
    cudaFuncSetAttribute(gemm_mma<4>, cudaFuncAttributeMaxDynamicSharedMemorySize, GEMM_SMEM);

    dim3 tb(32,8);

    // weight transposes -> single fp16 [N,K]
    tr_w<<<dim3(HH/32,  DD/32), tb>>>(v_w,  vw,  DD, HH);
    tr_w<<<dim3(NBASE/32, DD/32), tb>>>(mx_w, mxw, DD, NBASE);
    tr_w<<<dim3(DD/32,  HH/32), tb>>>(h_w,  hw,  HH, DD);

    // 1) layernorm (fp32 + fp16 hi/lo)
    ln_kernel<<<MROWS, 256>>>(x, ln_w, ln_b, xn, xnh, xnl);

    // 2) EMA -> mx hi/lo
    ema_kernel<<<(BB*DD)/256, 256>>>(xn, delta, alpha, beta_e, gamma_e, omega, mxh, mxl);

    // 3) v = silu(xn @ v_w + v_b)   fp32 out
    {
        EpiP P = {}; P.f0 = v; P.bias = v_b; P.ldc = HH;
        gemm_mma<0><<<dim3(HH/128, MROWS/128, 1), 256, GEMM_SMEM>>>(
            xnh, xnl, vw, DD, DD, DD, 0, 0, P);
    }
    tr_v<<<dim3(HH/32, LSEQ/32, BB), tb>>>(v, vT);

    // 4) base GEMM + split epilogue
    {
        EpiP P = {}; P.f0=u; P.f1=r; P.f2=hx;
        P.h0=qh; P.h1=ql; P.h2=kk;
        P.bias=mx_b; P.aux0=qk_g; P.aux1=qk_b;
        gemm_mma<1><<<dim3(NBASE/128, MROWS/128, 1), 256, GEMM_SMEM>>>(
            mxh, mxl, mxw, DD, DD, DD, 0, 0, P);
    }
    // 5) attn = laplace(q@k^T/L + bias) -> hi/lo
    {
        EpiP P = {}; P.h0 = ath; P.h1 = atl; P.aux0 = rel; P.ldc = LSEQ;
        P.strideC = (long)LSEQ*LSEQ;
        gemm_mma<2><<<dim3(LSEQ/128, LSEQ/128, BB), 256, GEMM_SMEM>>>(
            qh, ql, kk, ZZ, ZZ, ZZ, (long)LSEQ*ZZ, (long)LSEQ*ZZ, P);
    }
    // 6) hr = (attn @ vb) * r -> hi/lo (L,B,H)
    {
        EpiP P = {}; P.h0 = hrh; P.h1 = hrl; P.aux0 = r;
        gemm_mma<3><<<dim3(HH/128, LSEQ/128, BB), 256, GEMM_SMEM>>>(
            ath, atl, vT, LSEQ, LSEQ, LSEQ, (long)LSEQ*LSEQ, (long)HH*LSEQ, P);
    }
    // 7) out = x + u*(silu(hx + hr@h_w + h_b) - x)
    {
        EpiP P = {}; P.f0 = out; P.bias = h_b; P.aux0 = hx; P.aux1 = u; P.aux2 = x;
        gemm_mma<4><<<dim3(DD/128, MROWS/128, 1), 256, GEMM_SMEM>>>(
            hrh, hrl, hw, HH, HH, HH, 0, 0, P);
    }
}

// round 6
// speedup vs baseline: 5.6974x; 1.4665x over previous
#include <cuda_runtime.h>
#include <cuda_fp16.h>
#include <math.h>
#include <stdint.h>

// ---------------- problem constants ----------------
#define LSEQ 2048
#define BB   8
#define DD   1024
#define ZZ   128
#define HH   2048
#define NN   16
#define MROWS (LSEQ*BB)           // 16384
#define NBASE (ZZ+HH+2*DD)        // 4224

typedef __half h16;

// ---------------- scratch ----------------
// fp32
__device__ float g_xn [(size_t)MROWS*DD];
__device__ float g_v  [(size_t)MROWS*HH];
__device__ float g_u  [(size_t)MROWS*DD];
__device__ float g_r  [(size_t)MROWS*HH];
__device__ float g_hx [(size_t)MROWS*DD];
// fp16 operands (single precision term)
__device__ h16 g_xnh[(size_t)MROWS*DD];
__device__ h16 g_mxh[(size_t)MROWS*DD];
__device__ h16 g_qh [(size_t)BB*LSEQ*ZZ];
__device__ h16 g_ath[(size_t)BB*LSEQ*LSEQ];
__device__ h16 g_hrh[(size_t)MROWS*HH];
__device__ h16 g_vw [(size_t)HH*DD];
__device__ h16 g_mxw[(size_t)NBASE*DD];
__device__ h16 g_hw [(size_t)DD*HH];
__device__ h16 g_k  [(size_t)BB*LSEQ*ZZ];
__device__ h16 g_vT [(size_t)BB*HH*LSEQ];

// ---------------- math helpers ----------------
__device__ __forceinline__ float sigm_(float x){ return 1.f/(1.f+expf(-x)); }
__device__ __forceinline__ float silu_(float x){ return x/(1.f+expf(-x)); }
__device__ __forceinline__ float laplace_(float x){
    const float inv = (float)(1.0/(0.282095*1.4142135623730951));
    return 0.5f*(1.f + erff((x - 0.707107f) * inv));
}
__device__ __forceinline__ uint32_t sm_u32(const void* p){
    uint32_t a;
    asm("{ .reg .u64 t; cvta.to.shared.u64 t, %1; cvt.u32.u64 %0, t; }" : "=r"(a) : "l"(p));
    return a;
}
__device__ __forceinline__ void ldm4(uint32_t* r, uint32_t addr){
    asm volatile("ldmatrix.sync.aligned.m8n8.x4.shared.b16 {%0,%1,%2,%3}, [%4];"
        : "=r"(r[0]),"=r"(r[1]),"=r"(r[2]),"=r"(r[3]) : "r"(addr));
}
__device__ __forceinline__ void mma16816(float* c, const uint32_t* a, uint32_t b0, uint32_t b1){
    asm volatile("mma.sync.aligned.m16n8k16.row.col.f32.f16.f16.f32 "
        "{%0,%1,%2,%3}, {%4,%5,%6,%7}, {%8,%9}, {%0,%1,%2,%3};"
        : "+f"(c[0]),"+f"(c[1]),"+f"(c[2]),"+f"(c[3])
        : "r"(a[0]),"r"(a[1]),"r"(a[2]),"r"(a[3]),"r"(b0),"r"(b1));
}
#define CPA(dst, src) asm volatile("cp.async.cg.shared.global [%0], [%1], 16;" :: "r"(dst), "l"(src))

__device__ __forceinline__ void st2(h16* H, size_t idx, float v0, float v1){
    __half2 t; t.x=__float2half(v0); t.y=__float2half(v1);
    *(__half2*)(H+idx) = t;
}
__device__ __forceinline__ uint2 pack4(float4 v){
    uint2 h;
    h16 h0=__float2half(v.x), h1=__float2half(v.y), h2=__float2half(v.z), h3=__float2half(v.w);
    h.x = (uint32_t)__half_as_ushort(h0) | ((uint32_t)__half_as_ushort(h1)<<16);
    h.y = (uint32_t)__half_as_ushort(h2) | ((uint32_t)__half_as_ushort(h3)<<16);
    return h;
}

// ---------------- LayerNorm: fp32 out + fp16 ----------------
__global__ __launch_bounds__(256) void ln_kernel(
    const float* __restrict__ x, const float* __restrict__ w,
    const float* __restrict__ b, float* __restrict__ out,
    h16* __restrict__ oh)
{
    long row = blockIdx.x;
    int tid = threadIdx.x;
    float4 v = ((const float4*)(x + row*DD))[tid];
    float s  = v.x+v.y+v.z+v.w;
    float ss = fmaf(v.x,v.x, fmaf(v.y,v.y, fmaf(v.z,v.z, v.w*v.w)));
    #pragma unroll
    for (int o=16;o>0;o>>=1){
        s  += __shfl_xor_sync(0xffffffffu, s, o);
        ss += __shfl_xor_sync(0xffffffffu, ss, o);
    }
    __shared__ float sh0[8], sh1[8];
    int wid = tid>>5, lane = tid&31;
    if (lane==0){ sh0[wid]=s; sh1[wid]=ss; }
    __syncthreads();
    float S=0.f, SS=0.f;
    #pragma unroll
    for (int i=0;i<8;i++){ S += sh0[i]; SS += sh1[i]; }
    float mu  = S*(1.f/DD);
    float var = SS*(1.f/DD) - mu*mu;
    float inv = rsqrtf(var + 1e-5f);
    float4 wv = ((const float4*)w)[tid];
    float4 bv = ((const float4*)b)[tid];
    float4 o;
    o.x = (v.x-mu)*inv*wv.x + bv.x;
    o.y = (v.y-mu)*inv*wv.y + bv.y;
    o.z = (v.z-mu)*inv*wv.z + bv.z;
    o.w = (v.w-mu)*inv*wv.w + bv.w;
    ((float4*)(out + row*DD))[tid] = o;
    *(uint2*)(oh + row*DD + tid*4) = pack4(o);
}

// ---------------- EMA -> mx fp16 ----------------
__global__ __launch_bounds__(256) void ema_kernel(
    const float* __restrict__ xn,
    const float* __restrict__ delta, const float* __restrict__ alpha,
    const float* __restrict__ beta_e, const float* __restrict__ gamma_e,
    const float* __restrict__ omega,
    h16* __restrict__ mh)
{
    int gid = blockIdx.x*blockDim.x + threadIdx.x;   // b*1024+d
    int d = gid & (DD-1);
    float q[NN], pb[NN], g[NN], s[NN];
    #pragma unroll
    for (int n=0;n<NN;n++){
        float de = delta[d*NN+n];
        float p  = sigm_(de);
        q[n]  = 1.f - p*sigm_(alpha[d*NN+n]);
        pb[n] = p*beta_e[d*NN+n];
        g[n]  = gamma_e[d*NN+n]*0.25f;
        s[n]  = 0.f;
    }
    float om = omega[d];
    const float* xp = xn + gid;
    for (int l0=0; l0<LSEQ; l0+=8){
        float xv[8];
        #pragma unroll
        for (int i=0;i<8;i++) xv[i] = xp[(size_t)(l0+i)*(BB*DD)];
        #pragma unroll
        for (int i=0;i<8;i++){
            float xc = xv[i];
            float a0=0.f,a1=0.f,a2=0.f,a3=0.f;
            #pragma unroll
            for (int n=0;n<NN;n+=4){
                s[n]   = fmaf(q[n],   s[n],   pb[n]*xc);
                s[n+1] = fmaf(q[n+1], s[n+1], pb[n+1]*xc);
                s[n+2] = fmaf(q[n+2], s[n+2], pb[n+2]*xc);
                s[n+3] = fmaf(q[n+3], s[n+3], pb[n+3]*xc);
                a0 = fmaf(g[n],   s[n],   a0);
                a1 = fmaf(g[n+1], s[n+1], a1);
                a2 = fmaf(g[n+2], s[n+2], a2);
                a3 = fmaf(g[n+3], s[n+3], a3);
            }
            float y = silu_((a0+a1)+(a2+a3) + om*xc);
            mh[(size_t)(l0+i)*(BB*DD) + gid] = __float2half(y);
        }
    }
}

// ---------------- transposes ----------------
__global__ __launch_bounds__(256) void tr_w(const float* __restrict__ in,
                                            h16* __restrict__ oh, int R, int C)
{
    __shared__ float t[32][33];
    int c0 = blockIdx.x*32, r0 = blockIdx.y*32;
    int tx = threadIdx.x, ty = threadIdx.y;
    #pragma unroll
    for (int k=0;k<4;k++)
        t[ty+8*k][tx] = in[(size_t)(r0+ty+8*k)*C + c0+tx];
    __syncthreads();
    #pragma unroll
    for (int k=0;k<4;k++)
        oh[(size_t)(c0+ty+8*k)*R + r0+tx] = __float2half(t[tx][ty+8*k]);
}

__global__ __launch_bounds__(256) void tr_v(const float* __restrict__ v,
                                            h16* __restrict__ oh)
{
    __shared__ float t[32][33];
    int h0 = blockIdx.x*32, l0 = blockIdx.y*32, b = blockIdx.z;
    int tx = threadIdx.x, ty = threadIdx.y;
    #pragma unroll
    for (int k=0;k<4;k++)
        t[ty+8*k][tx] = v[((size_t)(l0+ty+8*k)*8 + b)*HH + h0+tx];
    __syncthreads();
    #pragma unroll
    for (int k=0;k<4;k++)
        oh[(size_t)b*HH*LSEQ + (size_t)(h0+ty+8*k)*LSEQ + l0+tx] =
            __float2half(t[tx][ty+8*k]);
}

// ---------------- GEMM: cp.async + ldmatrix + fp16 HMMA, 128x128x32, 4 stages ----------------
struct EpiP {
    float* f0; float* f1; float* f2;
    h16* h0; h16* h2;
    const float* bias; const float* aux0; const float* aux1; const float* aux2;
    long strideC; int ldc;
};

#define STG 16384

template<int EPI>
__global__ __launch_bounds__(256,2) void gemm_mma(
    const h16* __restrict__ Ahg, const h16* __restrict__ Bhg,
    int lda, int ldb, int K, long sA, long sB, EpiP P)
{
    extern __shared__ char smch[];
    const uint32_t smb = sm_u32(smch);
    const int tid = threadIdx.x;
    const int w = tid>>5, lane = tid&31;
    const int m0 = blockIdx.y*128, n0 = blockIdx.x*128, bz = blockIdx.z;
    Ahg += (size_t)bz*sA;
    Bhg += (size_t)bz*sB;
    const int mw = (w&1)*64, nw = (w>>1)*32;

    // staging: thread -> row r (0..127), granules g0,g0+1 (16B) of each tile
    const int r  = tid>>1;
    const int g0 = (tid&1)*2;
    const int sw = (r>>1)&3;
    const uint32_t d0 = (uint32_t)(r*64 + ((g0     ^ sw)<<4));
    const uint32_t d1 = (uint32_t)(r*64 + (((g0+1) ^ sw)<<4));
    const h16* sAh = Ahg + (size_t)(m0+r)*lda + g0*8;
    const h16* sBh = Bhg + (size_t)(n0+r)*ldb + g0*8;

    auto issue = [&](int kt){
        uint32_t sb = smb + (uint32_t)(kt&3)*STG;
        const h16* a0 = sAh + (size_t)kt*32;
        const h16* b0 = sBh + (size_t)kt*32;
        CPA(sb+d0,       a0); CPA(sb+d1,       a0+8);
        CPA(sb+8192+d0,  b0); CPA(sb+8192+d1,  b0+8);
        asm volatile("cp.async.commit_group;");
    };

    // ldmatrix lane geometry
    const int ra   = lane&15;
    const int la16 = lane>>4;
    const int swA  = ((mw + ra)>>1)&3;
    const int rb   = (lane&7) + ((lane>>4)&1)*8;
    const int lb16 = (lane>>3)&1;
    const int swB  = ((nw + rb)>>1)&3;

    float acc[4][4][4];
    #pragma unroll
    for (int a=0;a<4;a++)
        #pragma unroll
        for (int n=0;n<4;n++)
            #pragma unroll
            for (int i=0;i<4;i++) acc[a][n][i]=0.f;

    const int nk = K/32;
    issue(0); issue(1); issue(2);

    for (int kt=0; kt<nk; kt++){
        if (kt+2 < nk) asm volatile("cp.async.wait_group 2;");
        else           asm volatile("cp.async.wait_group 0;");
        __syncthreads();
        if (kt+3 < nk) issue(kt+3);

        const uint32_t sb = smb + (uint32_t)(kt&3)*STG;
        #pragma unroll
        for (int ks=0; ks<2; ks++){
            uint32_t bh[2][4];
            #pragma unroll
            for (int p=0;p<2;p++){
                uint32_t bd = sb + 8192u +
                    (uint32_t)((nw+rb+p*16)*64 + (((ks*2+lb16)^swB)<<4));
                ldm4(bh[p], bd);
            }
            #pragma unroll
            for (int a=0;a<4;a++){
                uint32_t ah[4];
                uint32_t ad = sb +
                    (uint32_t)((mw+ra+a*16)*64 + (((ks*2+la16)^swA)<<4));
                ldm4(ah, ad);
                #pragma unroll
                for (int n=0;n<4;n++){
                    const int p=n>>1, q=(n&1)*2;
                    mma16816(acc[a][n], ah, bh[p][q], bh[p][q+1]);
                }
            }
        }
        // no trailing __syncthreads: next iteration's barrier orders stage reuse
    }

    // ---------------- epilogue ----------------
    #pragma unroll
    for (int a=0;a<4;a++){
        #pragma unroll
        for (int n=0;n<4;n++){
            const int gj = n0 + nw + n*8 + (lane&3)*2;
            #pragma unroll
            for (int half=0; half<2; half++){
                const int gi = m0 + mw + a*16 + (lane>>2) + half*8;
                float v0 = acc[a][n][half*2+0];
                float v1 = acc[a][n][half*2+1];
                if (EPI==0){
                    float2 o = { silu_(v0 + P.bias[gj]), silu_(v1 + P.bias[gj+1]) };
                    *(float2*)&P.f0[(size_t)gi*P.ldc + gj] = o;
                } else if (EPI==1){
                    v0 += P.bias[gj]; v1 += P.bias[gj+1];
                    if (n0 < DD){
                        float2 o = { sigm_(v0), sigm_(v1) };
                        *(float2*)&P.f0[(size_t)gi*DD + gj] = o;
                    } else if (n0 < DD+ZZ){
                        int zi = gj - DD;
                        int l = gi>>3, b = gi&7;
                        size_t qi = ((size_t)b*LSEQ + l)*ZZ + zi;
                        float z0 = silu_(v0), z1 = silu_(v1);
                        float q0 = z0*P.aux0[zi]   + P.aux1[zi];
                        float q1 = z1*P.aux0[zi+1] + P.aux1[zi+1];
                        float k0 = z0*P.aux0[ZZ+zi]   + P.aux1[ZZ+zi];
                        float k1 = z1*P.aux0[ZZ+zi+1] + P.aux1[ZZ+zi+1];
                        st2(P.h0, qi, q0, q1);
                        st2(P.h2, qi, k0, k1);
                    } else if (n0 < DD+ZZ+HH){
                        float2 o = { silu_(v0), silu_(v1) };
                        *(float2*)&P.f1[(size_t)gi*HH + (gj-(DD+ZZ))] = o;
                    } else {
                        float2 o = { v0, v1 };
                        *(float2*)&P.f2[(size_t)gi*DD + (gj-(DD+ZZ+HH))] = o;
                    }
                } else if (EPI==2){
                    const float invL = 1.0f/LSEQ;
                    const float* rel = P.aux0 + (LSEQ-1) - gi + gj;
                    float o0 = laplace_(v0*invL + rel[0]);
                    float o1 = laplace_(v1*invL + rel[1]);
                    st2(P.h0, (size_t)bz*P.strideC + (size_t)gi*P.ldc + gj, o0, o1);
                } else if (EPI==3){
                    size_t idx = ((size_t)gi*8 + bz)*HH + gj;
                    float2 rr = *(const float2*)&P.aux0[idx];
                    st2(P.h0, idx, v0*rr.x, v1*rr.y);
                } else {
                    size_t idx = (size_t)gi*DD + gj;
                    float2 hb  = *(const float2*)&P.bias[gj];
                    float2 hx2 = *(const float2*)&P.aux0[idx];
                    float2 u2  = *(const float2*)&P.aux1[idx];
                    float2 x2  = *(const float2*)&P.aux2[idx];
                    float t0 = silu_(hx2.x + v0 + hb.x);
                    float t1 = silu_(hx2.y + v1 + hb.y);
                    float2 o = { x2.x + u2.x*(t0-x2.x), x2.y + u2.y*(t1-x2.y) };
                    *(float2*)&P.f0[idx] = o;
                }
            }
        }
    }
}

// ---------------- host ----------------
static const int GEMM_SMEM = 4*STG;   // 65536

extern "C" void kernel_launch(void* const* d_in, const int* in_sizes, int n_in,
                              void* d_out, int out_size)
{
    const float* x      = (const float*)d_in[0];
    const float* delta  = (const float*)d_in[1];
    const float* alpha  = (const float*)d_in[2];
    const float* beta_e = (const float*)d_in[3];
    const float* gamma_e= (const float*)d_in[4];
    const float* omega  = (const float*)d_in[5];
    const float* v_w    = (const float*)d_in[6];
    const float* v_b    = (const float*)d_in[7];
    const float* mx_w   = (const float*)d_in[8];
    const float* mx_b   = (const float*)d_in[9];
    const float* h_w    = (const float*)d_in[10];
    const float* h_b    = (const float*)d_in[11];
    const float* qk_g   = (const float*)d_in[12];
    const float* qk_b   = (const float*)d_in[13];
    const float* rel    = (const float*)d_in[14];
    const float* ln_w   = (const float*)d_in[15];
    const float* ln_b   = (const float*)d_in[16];
    float* out = (float*)d_out;

    float *xn,*v,*u,*r,*hx;
    h16 *xnh,*mxh,*qh,*ath,*hrh,*vw,*mxw,*hw,*kk,*vT;
    cudaGetSymbolAddress((void**)&xn, g_xn);
    cudaGetSymbolAddress((void**)&v,  g_v);
    cudaGetSymbolAddress((void**)&u,  g_u);
    cudaGetSymbolAddress((void**)&r,  g_r);
    cudaGetSymbolAddress((void**)&hx, g_hx);
    cudaGetSymbolAddress((void**)&xnh, g_xnh);
    cudaGetSymbolAddress((void**)&mxh, g_mxh);
    cudaGetSymbolAddress((void**)&qh,  g_qh);
    cudaGetSymbolAddress((void**)&ath, g_ath);
    cudaGetSymbolAddress((void**)&hrh, g_hrh);
    cudaGetSymbolAddress((void**)&vw,  g_vw);
    cudaGetSymbolAddress((void**)&mxw, g_mxw);
    cudaGetSymbolAddress((void**)&hw,  g_hw);
    cudaGetSymbolAddress((void**)&kk,  g_k);
    cudaGetSymbolAddress((void**)&vT,  g_vT);

    cudaFuncSetAttribute(gemm_mma<0>, cudaFuncAttributeMaxDynamicSharedMemorySize, GEMM_SMEM);
    cudaFuncSetAttribute(gemm_mma<1>, cudaFuncAttributeMaxDynamicSharedMemorySize, GEMM_SMEM);
    cudaFuncSetAttribute(gemm_mma<2>, cudaFuncAttributeMaxDynamicSharedMemorySize, GEMM_SMEM);
    cudaFuncSetAttribute(gemm_mma<3>, cudaFuncAttributeMaxDynamicSharedMemorySize, GEMM_SMEM);
    cudaFuncSetAttribute(gemm_mma<4>, cudaFuncAttributeMaxDynamicSharedMemorySize, GEMM_SMEM);

    dim3 tb(32,8);

    // weight transposes -> single fp16 [N,K]
    tr_w<<<dim3(HH/32,  DD/32), tb>>>(v_w,  vw,  DD, HH);
    tr_w<<<dim3(NBASE/32, DD/32), tb>>>(mx_w, mxw, DD, NBASE);
    tr_w<<<dim3(DD/32,  HH/32), tb>>>(h_w,  hw,  HH, DD);

    // 1) layernorm (fp32 + fp16)
    ln_kernel<<<MROWS, 256>>>(x, ln_w, ln_b, xn, xnh);

    // 2) EMA -> mx fp16
    ema_kernel<<<(BB*DD)/256, 256>>>(xn, delta, alpha, beta_e, gamma_e, omega, mxh);

    // 3) v = silu(xn @ v_w + v_b)   fp32 out
    {
        EpiP P = {}; P.f0 = v; P.bias = v_b; P.ldc = HH;
        gemm_mma<0><<<dim3(HH/128, MROWS/128, 1), 256, GEMM_SMEM>>>(
            xnh, vw, DD, DD, DD, 0, 0, P);
    }
    tr_v<<<dim3(HH/32, LSEQ/32, BB), tb>>>(v, vT);

    // 4) base GEMM + split epilogue
    {
        EpiP P = {}; P.f0=u; P.f1=r; P.f2=hx;
        P.h0=qh; P.h2=kk;
        P.bias=mx_b; P.aux0=qk_g; P.aux1=qk_b;
        gemm_mma<1><<<dim3(NBASE/128, MROWS/128, 1), 256, GEMM_SMEM>>>(
            mxh, mxw, DD, DD, DD, 0, 0, P);
    }
    // 5) attn = laplace(q@k^T/L + bias) -> fp16
    {
        EpiP P = {}; P.h0 = ath; P.aux0 = rel; P.ldc = LSEQ;
        P.strideC = (long)LSEQ*LSEQ;
        gemm_mma<2><<<dim3(LSEQ/128, LSEQ/128, BB), 256, GEMM_SMEM>>>(
            qh, kk, ZZ, ZZ, ZZ, (long)LSEQ*ZZ, (long)LSEQ*ZZ, P);
    }
    // 6) hr = (attn @ vb) * r -> fp16 (L,B,H)
    {
        EpiP P = {}; P.h0 = hrh; P.aux0 = r;
        gemm_mma<3><<<dim3(HH/128, LSEQ/128, BB), 256, GEMM_SMEM>>>(
            ath, vT, LSEQ, LSEQ, LSEQ, (long)LSEQ*LSEQ, (long)HH*LSEQ, P);
    }
    // 7) out = x + u*(silu(hx + hr@h_w + h_b) - x)
    {
        EpiP P = {}; P.f0 = out; P.bias = h_b; P.aux0 = hx; P.aux1 = u; P.aux2 = x;
        gemm_mma<4><<<dim3(DD/128, MROWS/128, 1), 256, GEMM_SMEM>>>(
            hrh, hw, HH, HH, HH, 0, 0, P);
    }
}